// round 1
// baseline (speedup 1.0000x reference)
#include <cuda_runtime.h>

// Problem constants
#define Bq   4
#define Tq   2048
#define Dq   1024
#define Hq   16
#define HDq  64
#define Mq   (Bq * Tq)        // 8192 rows
#define DFF  (4 * Dq)         // 4096
#define LN_EPS 1e-5f
#define ATT_SCALE 0.125f      // HD^-0.5 = 1/8

// ---------------------------------------------------------------------------
// Scratch (static device globals: allocation-free, graph-capture safe)
// ---------------------------------------------------------------------------
__device__ float g_h[Mq * Dq];            // LN output (reused for LN1 and LN2)
__device__ float g_wqkv[Dq * 3 * Dq];     // Wq|Wk|Wv repacked to [D, 3D]
__device__ float g_qkv[Mq * 3 * Dq];      // fused QKV projection output
__device__ float g_attn[Mq * Dq];         // attention output (heads concat)
__device__ float g_x1[Mq * Dq];           // residual-1 output
__device__ float g_ff[Mq * DFF];          // FFN hidden

// ---------------------------------------------------------------------------
// Repack Wq/Wk/Wv [H,D,HD] into a single [D, 3*D] row-major matrix so the
// QKV projection is one GEMM. Column c = s*1024 + h*64 + k  (s: 0=q,1=k,2=v)
// ---------------------------------------------------------------------------
__global__ void prep_wqkv(const float* __restrict__ Wq,
                          const float* __restrict__ Wk,
                          const float* __restrict__ Wv,
                          float* __restrict__ out)
{
    int i = blockIdx.x * blockDim.x + threadIdx.x;
    if (i >= Dq * 3 * Dq) return;
    int d  = i / (3 * Dq);
    int c  = i % (3 * Dq);
    int s  = c / Dq;
    int hc = c % Dq;
    int h  = hc / HDq;
    int k  = hc % HDq;
    const float* W = (s == 0) ? Wq : (s == 1) ? Wk : Wv;
    out[i] = W[((long)h * Dq + d) * HDq + k];
}

// ---------------------------------------------------------------------------
// LayerNorm: one block per row of 1024, 256 threads, float4 per thread
// ---------------------------------------------------------------------------
__global__ void ln_kernel(const float* __restrict__ x,
                          const float* __restrict__ g,
                          const float* __restrict__ b,
                          float* __restrict__ out)
{
    __shared__ float red[16];
    int row = blockIdx.x;
    int t = threadIdx.x;                       // 256 threads
    const float4* xr = (const float4*)(x + (long)row * Dq);
    float4 v = xr[t];
    float s  = v.x + v.y + v.z + v.w;
    float ss = v.x * v.x + v.y * v.y + v.z * v.z + v.w * v.w;
    #pragma unroll
    for (int o = 16; o >= 1; o >>= 1) {
        s  += __shfl_xor_sync(0xffffffffu, s,  o);
        ss += __shfl_xor_sync(0xffffffffu, ss, o);
    }
    if ((t & 31) == 0) { red[t >> 5] = s; red[8 + (t >> 5)] = ss; }
    __syncthreads();
    float stot = 0.f, sstot = 0.f;
    #pragma unroll
    for (int w = 0; w < 8; w++) { stot += red[w]; sstot += red[8 + w]; }
    float mu  = stot * (1.f / Dq);
    float var = sstot * (1.f / Dq) - mu * mu;
    float inv = rsqrtf(var + LN_EPS);
    float4 gg = ((const float4*)g)[t];
    float4 bb = ((const float4*)b)[t];
    float4 o4;
    o4.x = (v.x - mu) * inv * gg.x + bb.x;
    o4.y = (v.y - mu) * inv * gg.y + bb.y;
    o4.z = (v.z - mu) * inv * gg.z + bb.z;
    o4.w = (v.w - mu) * inv * gg.w + bb.w;
    ((float4*)(out + (long)row * Dq))[t] = o4;
}

// ---------------------------------------------------------------------------
// SGEMM: C[M,N] = A[M,K] @ B[K,N] (+epilogue). 128x128 block, BK=8,
// 256 threads, 8x8 per-thread microtile, float4 global loads.
// EPI: 0 = none, 1 = +bias, 2 = +bias+residual, 3 = +bias+relu
// ---------------------------------------------------------------------------
template <int EPI>
__global__ void sgemm(const float* __restrict__ A,
                      const float* __restrict__ Bm,
                      const float* __restrict__ bias,
                      const float* __restrict__ res,
                      float* __restrict__ C,
                      int N, int K)
{
    __shared__ float As[8][128];
    __shared__ float Bs[8][128];

    const int tid = threadIdx.x;
    const int bm = blockIdx.y, bn = blockIdx.x;
    const float* Ablk = A + (long)bm * 128 * K;
    const float* Bblk = Bm + bn * 128;

    const int arow = tid >> 1;            // 0..127
    const int acol = (tid & 1) * 4;       // 0 or 4
    const int brow = tid >> 5;            // 0..7
    const int bcol = (tid & 31) * 4;      // 0..124
    const int tr = (tid >> 4) * 8;        // 0..120 step 8
    const int tc = (tid & 15) * 8;

    float acc[8][8];
    #pragma unroll
    for (int i = 0; i < 8; i++)
        #pragma unroll
        for (int j = 0; j < 8; j++) acc[i][j] = 0.f;

    for (int k0 = 0; k0 < K; k0 += 8) {
        float4 av = *(const float4*)(Ablk + (long)arow * K + k0 + acol);
        float4 bv = *(const float4*)(Bblk + (long)(k0 + brow) * N + bcol);
        __syncthreads();
        As[acol + 0][arow] = av.x;
        As[acol + 1][arow] = av.y;
        As[acol + 2][arow] = av.z;
        As[acol + 3][arow] = av.w;
        *(float4*)&Bs[brow][bcol] = bv;
        __syncthreads();
        #pragma unroll
        for (int kk = 0; kk < 8; kk++) {
            float a[8], bb[8];
            *(float4*)&a[0]  = *(const float4*)&As[kk][tr];
            *(float4*)&a[4]  = *(const float4*)&As[kk][tr + 4];
            *(float4*)&bb[0] = *(const float4*)&Bs[kk][tc];
            *(float4*)&bb[4] = *(const float4*)&Bs[kk][tc + 4];
            #pragma unroll
            for (int i = 0; i < 8; i++)
                #pragma unroll
                for (int j = 0; j < 8; j++)
                    acc[i][j] += a[i] * bb[j];
        }
    }

    const int crow0 = bm * 128 + tr;
    const int ccol0 = bn * 128 + tc;
    #pragma unroll
    for (int i = 0; i < 8; i++) {
        long roff = (long)(crow0 + i) * N + ccol0;
        #pragma unroll
        for (int j = 0; j < 8; j += 4) {
            float4 v = make_float4(acc[i][j], acc[i][j+1], acc[i][j+2], acc[i][j+3]);
            if (EPI >= 1) {
                float4 bv = *(const float4*)(bias + ccol0 + j);
                v.x += bv.x; v.y += bv.y; v.z += bv.z; v.w += bv.w;
            }
            if (EPI == 2) {
                float4 rv = *(const float4*)(res + roff + j);
                v.x += rv.x; v.y += rv.y; v.z += rv.z; v.w += rv.w;
            }
            if (EPI == 3) {
                v.x = fmaxf(v.x, 0.f); v.y = fmaxf(v.y, 0.f);
                v.z = fmaxf(v.z, 0.f); v.w = fmaxf(v.w, 0.f);
            }
            *(float4*)(C + roff + j) = v;
        }
    }
}

// ---------------------------------------------------------------------------
// Flash attention (fp32, online softmax). One block per (q-tile of 64, b*h).
// Shared: Q[64][68], K/P[64][68] (K overwritten by P), V[64][64]. 256 threads,
// thread (tr,tc) owns a 4x4 patch of the 64x64 S/O tiles.
// qkv layout: row m = b*T+t, 3072 cols: [q | k | v], each h*64+hd.
// ---------------------------------------------------------------------------
__global__ void flash_kernel(const float* __restrict__ qkv,
                             float* __restrict__ out)
{
    extern __shared__ float sm[];
    float* Qs = sm;               // 64 x 68
    float* KP = sm + 64 * 68;     // 64 x 68 (K tile, then reused for P)
    float* Vs = sm + 2 * 64 * 68; // 64 x 64

    const int qi  = blockIdx.x;
    const int bh  = blockIdx.y;
    const int b   = bh >> 4;
    const int h   = bh & 15;
    const int tid = threadIdx.x;
    const int tr  = tid >> 4;      // 0..15
    const int tc  = tid & 15;      // 0..15
    const int lr  = tid >> 2;      // 0..63 (load row)
    const int lc  = (tid & 3) << 4;// 0,16,32,48

    const float* base = qkv + (long)b * Tq * (3 * Dq) + h * HDq;

    // Load & pre-scale Q tile
    {
        const float* src = base + (long)(qi * 64 + lr) * (3 * Dq) + lc;
        #pragma unroll
        for (int u = 0; u < 4; u++) {
            float4 v = *(const float4*)(src + u * 4);
            v.x *= ATT_SCALE; v.y *= ATT_SCALE; v.z *= ATT_SCALE; v.w *= ATT_SCALE;
            *(float4*)(Qs + lr * 68 + lc + u * 4) = v;
        }
    }

    float m[4], l[4], o[4][4];
    #pragma unroll
    for (int i = 0; i < 4; i++) {
        m[i] = -1e30f; l[i] = 0.f;
        #pragma unroll
        for (int j = 0; j < 4; j++) o[i][j] = 0.f;
    }

    for (int jt = 0; jt <= qi; jt++) {
        __syncthreads();
        {   // load K and V tiles
            const float* ks = base + (long)(jt * 64 + lr) * (3 * Dq) + Dq + lc;
            #pragma unroll
            for (int u = 0; u < 4; u++) {
                *(float4*)(KP + lr * 68 + lc + u * 4) = *(const float4*)(ks + u * 4);
                *(float4*)(Vs + lr * 64 + lc + u * 4) = *(const float4*)(ks + Dq + u * 4);
            }
        }
        __syncthreads();

        // S = Q K^T (Q already scaled)
        float s[4][4];
        #pragma unroll
        for (int i = 0; i < 4; i++)
            #pragma unroll
            for (int j = 0; j < 4; j++) s[i][j] = 0.f;
        #pragma unroll 4
        for (int k = 0; k < 64; k += 4) {
            float4 qv[4], kv[4];
            #pragma unroll
            for (int i = 0; i < 4; i++) qv[i] = *(const float4*)(Qs + (tr * 4 + i) * 68 + k);
            #pragma unroll
            for (int j = 0; j < 4; j++) kv[j] = *(const float4*)(KP + (tc * 4 + j) * 68 + k);
            #pragma unroll
            for (int i = 0; i < 4; i++)
                #pragma unroll
                for (int j = 0; j < 4; j++)
                    s[i][j] += qv[i].x * kv[j].x + qv[i].y * kv[j].y
                             + qv[i].z * kv[j].z + qv[i].w * kv[j].w;
        }

        // causal mask on the diagonal tile
        if (jt == qi) {
            #pragma unroll
            for (int i = 0; i < 4; i++)
                #pragma unroll
                for (int j = 0; j < 4; j++)
                    if (tc * 4 + j > tr * 4 + i) s[i][j] = -1e30f;
        }

        // online softmax (row stats reduced across the 16-thread tc group)
        float alpha[4];
        #pragma unroll
        for (int i = 0; i < 4; i++) {
            float mx = fmaxf(fmaxf(s[i][0], s[i][1]), fmaxf(s[i][2], s[i][3]));
            #pragma unroll
            for (int off = 8; off >= 1; off >>= 1)
                mx = fmaxf(mx, __shfl_xor_sync(0xffffffffu, mx, off));
            float mn = fmaxf(m[i], mx);
            alpha[i] = __expf(m[i] - mn);
            m[i] = mn;
            float rs = 0.f;
            #pragma unroll
            for (int j = 0; j < 4; j++) { s[i][j] = __expf(s[i][j] - mn); rs += s[i][j]; }
            #pragma unroll
            for (int off = 8; off >= 1; off >>= 1)
                rs += __shfl_xor_sync(0xffffffffu, rs, off);
            l[i] = l[i] * alpha[i] + rs;
            #pragma unroll
            for (int j = 0; j < 4; j++) o[i][j] *= alpha[i];
        }

        __syncthreads();  // everyone done reading K before P overwrites it
        #pragma unroll
        for (int i = 0; i < 4; i++)
            #pragma unroll
            for (int j = 0; j < 4; j++)
                KP[(tr * 4 + i) * 68 + tc * 4 + j] = s[i][j];
        __syncthreads();

        // O += P @ V
        #pragma unroll 4
        for (int c = 0; c < 64; c++) {
            float4 v4 = *(const float4*)(Vs + c * 64 + tc * 4);
            #pragma unroll
            for (int i = 0; i < 4; i++) {
                float p = KP[(tr * 4 + i) * 68 + c];
                o[i][0] += p * v4.x; o[i][1] += p * v4.y;
                o[i][2] += p * v4.z; o[i][3] += p * v4.w;
            }
        }
    }

    // finalize and store concat-head layout [B*T, D]
    #pragma unroll
    for (int i = 0; i < 4; i++) {
        float inv = 1.f / l[i];
        float4 v = make_float4(o[i][0] * inv, o[i][1] * inv, o[i][2] * inv, o[i][3] * inv);
        *(float4*)(out + (long)(b * Tq + qi * 64 + tr * 4 + i) * Dq + h * HDq + tc * 4) = v;
    }
}

// ---------------------------------------------------------------------------
// Launch
// ---------------------------------------------------------------------------
extern "C" void kernel_launch(void* const* d_in, const int* in_sizes, int n_in,
                              void* d_out, int out_size)
{
    const float* x   = (const float*)d_in[0];
    const float* Wq  = (const float*)d_in[1];
    const float* Wk  = (const float*)d_in[2];
    const float* Wv  = (const float*)d_in[3];
    const float* Wp  = (const float*)d_in[4];
    const float* bp  = (const float*)d_in[5];
    const float* W1  = (const float*)d_in[6];
    const float* b1  = (const float*)d_in[7];
    const float* W2  = (const float*)d_in[8];
    const float* b2  = (const float*)d_in[9];
    const float* g1  = (const float*)d_in[10];
    const float* be1 = (const float*)d_in[11];
    const float* g2  = (const float*)d_in[12];
    const float* be2 = (const float*)d_in[13];
    float* out = (float*)d_out;

    float *p_h, *p_wqkv, *p_qkv, *p_attn, *p_x1, *p_ff;
    cudaGetSymbolAddress((void**)&p_h,    g_h);
    cudaGetSymbolAddress((void**)&p_wqkv, g_wqkv);
    cudaGetSymbolAddress((void**)&p_qkv,  g_qkv);
    cudaGetSymbolAddress((void**)&p_attn, g_attn);
    cudaGetSymbolAddress((void**)&p_x1,   g_x1);
    cudaGetSymbolAddress((void**)&p_ff,   g_ff);

    const int flash_smem = (2 * 64 * 68 + 64 * 64) * (int)sizeof(float); // 51200 B
    cudaFuncSetAttribute(flash_kernel, cudaFuncAttributeMaxDynamicSharedMemorySize,
                         flash_smem);

    // 1) repack QKV weights into [D, 3D]
    prep_wqkv<<<(Dq * 3 * Dq + 255) / 256, 256>>>(Wq, Wk, Wv, p_wqkv);
    // 2) LN1
    ln_kernel<<<Mq, 256>>>(x, g1, be1, p_h);
    // 3) fused QKV projection: [8192,1024] @ [1024,3072]
    sgemm<0><<<dim3(3 * Dq / 128, Mq / 128), 256>>>(p_h, p_wqkv, nullptr, nullptr,
                                                    p_qkv, 3 * Dq, Dq);
    // 4) flash attention -> [8192,1024] (heads concatenated)
    flash_kernel<<<dim3(Tq / 64, Bq * Hq), 256, flash_smem>>>(p_qkv, p_attn);
    // 5) output projection + bias + residual(x)
    sgemm<2><<<dim3(Dq / 128, Mq / 128), 256>>>(p_attn, Wp, bp, x, p_x1, Dq, Dq);
    // 6) LN2
    ln_kernel<<<Mq, 256>>>(p_x1, g2, be2, p_h);
    // 7) FFN up + bias + relu: [8192,1024] @ [1024,4096]
    sgemm<3><<<dim3(DFF / 128, Mq / 128), 256>>>(p_h, W1, b1, nullptr, p_ff, DFF, Dq);
    // 8) FFN down + bias + residual(x1) -> d_out
    sgemm<2><<<dim3(Dq / 128, Mq / 128), 256>>>(p_ff, W2, b2, p_x1, out, Dq, DFF);
}

// round 2
// speedup vs baseline: 1.7226x; 1.7226x over previous
#include <cuda_runtime.h>
#include <cuda_bf16.h>
#include <stdint.h>

// Problem constants
#define Bq   4
#define Tq   2048
#define Dq   1024
#define Hq   16
#define HDq  64
#define Mq   (Bq * Tq)        // 8192 rows
#define DFF  (4 * Dq)         // 4096
#define LN_EPS 1e-5f
#define ATT_SCALE 0.125f      // HD^-0.5

// ---------------------------------------------------------------------------
// Scratch (static device globals: allocation-free, graph-capture safe)
// ---------------------------------------------------------------------------
__device__ __nv_bfloat16 g_h_hi[Mq * Dq],    g_h_lo[Mq * Dq];        // LN out (split)
__device__ __nv_bfloat16 g_wqkv_hi[3*Dq*Dq], g_wqkv_lo[3*Dq*Dq];     // [3D][D] (N-major)
__device__ __nv_bfloat16 g_wp_hi[Dq*Dq],     g_wp_lo[Dq*Dq];         // [D][D] transposed
__device__ __nv_bfloat16 g_w1_hi[Dq*DFF],    g_w1_lo[Dq*DFF];        // [4D][D] transposed
__device__ __nv_bfloat16 g_w2_hi[DFF*Dq],    g_w2_lo[DFF*Dq];        // [D][4D] transposed
__device__ float         g_qkv[Mq * 3 * Dq];                          // QKV fp32 (flash input)
__device__ __nv_bfloat16 g_attn_hi[Mq * Dq], g_attn_lo[Mq * Dq];     // attn out (split)
__device__ float         g_x1[Mq * Dq];                               // residual-1
__device__ __nv_bfloat16 g_ff_hi[Mq * DFF],  g_ff_lo[Mq * DFF];      // FFN hidden (split)

// ---------------------------------------------------------------------------
// Helpers
// ---------------------------------------------------------------------------
__device__ __forceinline__ void split_bf16(float v, __nv_bfloat16& hi, __nv_bfloat16& lo) {
    hi = __float2bfloat16(v);
    lo = __float2bfloat16(v - __bfloat162float(hi));
}

__device__ __forceinline__ void mma16816(float* c, const uint32_t* a, const uint32_t* b) {
    asm volatile(
        "mma.sync.aligned.m16n8k16.row.col.f32.bf16.bf16.f32 "
        "{%0,%1,%2,%3}, {%4,%5,%6,%7}, {%8,%9}, {%0,%1,%2,%3};"
        : "+f"(c[0]), "+f"(c[1]), "+f"(c[2]), "+f"(c[3])
        : "r"(a[0]), "r"(a[1]), "r"(a[2]), "r"(a[3]), "r"(b[0]), "r"(b[1]));
}

__device__ __forceinline__ void cp16(void* sdst, const void* gsrc) {
    unsigned sa = (unsigned)__cvta_generic_to_shared(sdst);
    asm volatile("cp.async.cg.shared.global [%0], [%1], 16;" :: "r"(sa), "l"(gsrc));
}
#define CP_COMMIT() asm volatile("cp.async.commit_group;")
#define CP_WAIT0()  asm volatile("cp.async.wait_group 0;")

// ---------------------------------------------------------------------------
// Weight prep: split + transpose to [N][K] bf16 hi/lo
// ---------------------------------------------------------------------------
__global__ void prep_wqkv_t(const float* __restrict__ Wq,
                            const float* __restrict__ Wk,
                            const float* __restrict__ Wv,
                            __nv_bfloat16* __restrict__ o_hi,
                            __nv_bfloat16* __restrict__ o_lo)
{
    int i = blockIdx.x * blockDim.x + threadIdx.x;
    if (i >= 3 * Dq * Dq) return;
    int n = i / Dq;            // qkv column 0..3071
    int d = i % Dq;            // input dim (GEMM K)
    int s = n >> 10;
    int hc = n & 1023;
    int h = hc >> 6, hd = hc & 63;
    const float* W = (s == 0) ? Wq : (s == 1) ? Wk : Wv;
    float v = W[((long)h * Dq + d) * HDq + hd];
    split_bf16(v, o_hi[i], o_lo[i]);
}

// in: [K][N] fp32  ->  out: [N][K] bf16 hi/lo
__global__ void transpose_split(const float* __restrict__ in,
                                __nv_bfloat16* __restrict__ o_hi,
                                __nv_bfloat16* __restrict__ o_lo,
                                int K, int N)
{
    long i = (long)blockIdx.x * blockDim.x + threadIdx.x;
    if (i >= (long)K * N) return;
    int n = (int)(i / K);
    int k = (int)(i % K);
    float v = in[(long)k * N + n];
    split_bf16(v, o_hi[i], o_lo[i]);
}

// ---------------------------------------------------------------------------
// LayerNorm: one block per row of 1024, 256 threads; outputs split bf16
// ---------------------------------------------------------------------------
__global__ void ln_split_kernel(const float* __restrict__ x,
                                const float* __restrict__ g,
                                const float* __restrict__ b,
                                __nv_bfloat16* __restrict__ o_hi,
                                __nv_bfloat16* __restrict__ o_lo)
{
    __shared__ float red[16];
    int row = blockIdx.x;
    int t = threadIdx.x;
    const float4* xr = (const float4*)(x + (long)row * Dq);
    float4 v = xr[t];
    float s  = v.x + v.y + v.z + v.w;
    float ss = v.x * v.x + v.y * v.y + v.z * v.z + v.w * v.w;
    #pragma unroll
    for (int o = 16; o >= 1; o >>= 1) {
        s  += __shfl_xor_sync(0xffffffffu, s,  o);
        ss += __shfl_xor_sync(0xffffffffu, ss, o);
    }
    if ((t & 31) == 0) { red[t >> 5] = s; red[8 + (t >> 5)] = ss; }
    __syncthreads();
    float stot = 0.f, sstot = 0.f;
    #pragma unroll
    for (int w = 0; w < 8; w++) { stot += red[w]; sstot += red[8 + w]; }
    float mu  = stot * (1.f / Dq);
    float var = sstot * (1.f / Dq) - mu * mu;
    float inv = rsqrtf(var + LN_EPS);
    float4 gg = ((const float4*)g)[t];
    float4 bb = ((const float4*)b)[t];
    float o0 = (v.x - mu) * inv * gg.x + bb.x;
    float o1 = (v.y - mu) * inv * gg.y + bb.y;
    float o2 = (v.z - mu) * inv * gg.z + bb.z;
    float o3 = (v.w - mu) * inv * gg.w + bb.w;
    __nv_bfloat16 h0,l0,h1,l1,h2,l2,h3,l3;
    split_bf16(o0,h0,l0); split_bf16(o1,h1,l1);
    split_bf16(o2,h2,l2); split_bf16(o3,h3,l3);
    long base = (long)row * Dq + t * 4;
    *(__nv_bfloat162*)(o_hi + base)     = __nv_bfloat162(h0, h1);
    *(__nv_bfloat162*)(o_hi + base + 2) = __nv_bfloat162(h2, h3);
    *(__nv_bfloat162*)(o_lo + base)     = __nv_bfloat162(l0, l1);
    *(__nv_bfloat162*)(o_lo + base + 2) = __nv_bfloat162(l2, l3);
}

// ---------------------------------------------------------------------------
// bf16x3 tensor-core GEMM: C[M,N] = A[M,K] @ B[K,N]
//   A given as split bf16 [M][K]; B given as split bf16 PRE-TRANSPOSED [N][K].
//   D = Ahi*Bhi + Ahi*Blo + Alo*Bhi (fp32 accumulate) ~ fp32 accuracy.
// 128x128 block, BK=32, 256 threads (8 warps, 2x4), warp tile 64x32,
// cp.async double buffering. Smem rows padded to 40 bf16 (conflict-free frags).
// EPI: 0 = fp32 out; 2 = +bias+residual fp32 out; 3 = +bias+relu -> split bf16 out
// ---------------------------------------------------------------------------
#define KPAD 40
#define TILE_E (128 * KPAD)          // elems per (matrix, part) per stage

template <int EPI>
__global__ void __launch_bounds__(256)
gemm_bf16x3(const __nv_bfloat16* __restrict__ Ahi,
            const __nv_bfloat16* __restrict__ Alo,
            const __nv_bfloat16* __restrict__ Bhi,
            const __nv_bfloat16* __restrict__ Blo,
            const float* __restrict__ bias,
            const float* __restrict__ res,
            float* __restrict__ C,
            __nv_bfloat16* __restrict__ Chi,
            __nv_bfloat16* __restrict__ Clo,
            int N, int K)
{
    extern __shared__ __nv_bfloat16 smem[];
    // layout: [stage][0=A,1=B][0=hi,1=lo][128][KPAD]
    const int tid  = threadIdx.x;
    const int lane = tid & 31;
    const int warp = tid >> 5;
    const int wm = warp >> 2;          // 0..1
    const int wn = warp & 3;           // 0..3
    const int fr = lane >> 2;          // 0..7
    const int fc = (lane & 3) * 2;     // 0,2,4,6

    const int bm = blockIdx.y, bn = blockIdx.x;
    const __nv_bfloat16* Ahi_b = Ahi + (long)bm * 128 * K;
    const __nv_bfloat16* Alo_b = Alo + (long)bm * 128 * K;
    const __nv_bfloat16* Bhi_b = Bhi + (long)bn * 128 * K;
    const __nv_bfloat16* Blo_b = Blo + (long)bn * 128 * K;

    const int r0  = tid >> 2;          // 0..63
    const int seg = (tid & 3) * 8;     // element offset of 16B chunk

    auto sbase = [&](int st, int ab, int p) -> __nv_bfloat16* {
        return smem + (((st * 2) + ab) * 2 + p) * TILE_E;
    };

    auto ld_tile = [&](int st, int kt) {
        long k0 = (long)kt * 32;
        #pragma unroll
        for (int rr = 0; rr < 2; rr++) {
            int r = r0 + rr * 64;
            long go = (long)r * K + k0 + seg;
            int  so = r * KPAD + seg;
            cp16(sbase(st,0,0) + so, Ahi_b + go);
            cp16(sbase(st,0,1) + so, Alo_b + go);
            cp16(sbase(st,1,0) + so, Bhi_b + go);
            cp16(sbase(st,1,1) + so, Blo_b + go);
        }
    };

    float acc[4][4][4];
    #pragma unroll
    for (int i = 0; i < 4; i++)
        #pragma unroll
        for (int j = 0; j < 4; j++)
            #pragma unroll
            for (int r = 0; r < 4; r++) acc[i][j][r] = 0.f;

    const int KT = K / 32;
    ld_tile(0, 0);
    CP_COMMIT();

    for (int kt = 0; kt < KT; kt++) {
        CP_WAIT0();
        __syncthreads();
        if (kt + 1 < KT) {
            ld_tile((kt + 1) & 1, kt + 1);
            CP_COMMIT();
        }
        const int st = kt & 1;
        const __nv_bfloat16* sAh = sbase(st, 0, 0);
        const __nv_bfloat16* sAl = sbase(st, 0, 1);
        const __nv_bfloat16* sBh = sbase(st, 1, 0);
        const __nv_bfloat16* sBl = sbase(st, 1, 1);

        #pragma unroll
        for (int ks = 0; ks < 2; ks++) {
            uint32_t ah[4][4], al[4][4], bh[4][2], bl[4][2];
            #pragma unroll
            for (int mt = 0; mt < 4; mt++) {
                int row = wm * 64 + mt * 16 + fr;
                int col = ks * 16 + fc;
                const __nv_bfloat16* pa = sAh + row * KPAD + col;
                const __nv_bfloat16* pl = sAl + row * KPAD + col;
                ah[mt][0] = *(const uint32_t*)pa;
                ah[mt][1] = *(const uint32_t*)(pa + 8 * KPAD);
                ah[mt][2] = *(const uint32_t*)(pa + 8);
                ah[mt][3] = *(const uint32_t*)(pa + 8 * KPAD + 8);
                al[mt][0] = *(const uint32_t*)pl;
                al[mt][1] = *(const uint32_t*)(pl + 8 * KPAD);
                al[mt][2] = *(const uint32_t*)(pl + 8);
                al[mt][3] = *(const uint32_t*)(pl + 8 * KPAD + 8);
            }
            #pragma unroll
            for (int nt = 0; nt < 4; nt++) {
                int n = wn * 32 + nt * 8 + fr;
                int k = ks * 16 + fc;
                const __nv_bfloat16* pb = sBh + n * KPAD + k;
                const __nv_bfloat16* pq = sBl + n * KPAD + k;
                bh[nt][0] = *(const uint32_t*)pb;
                bh[nt][1] = *(const uint32_t*)(pb + 8);
                bl[nt][0] = *(const uint32_t*)pq;
                bl[nt][1] = *(const uint32_t*)(pq + 8);
            }
            #pragma unroll
            for (int mt = 0; mt < 4; mt++)
                #pragma unroll
                for (int nt = 0; nt < 4; nt++) {
                    mma16816(acc[mt][nt], ah[mt], bh[nt]);
                    mma16816(acc[mt][nt], ah[mt], bl[nt]);
                    mma16816(acc[mt][nt], al[mt], bh[nt]);
                }
        }
        __syncthreads();
    }

    // epilogue
    const int lr4 = lane >> 2;
    const int lc2 = (lane & 3) * 2;
    #pragma unroll
    for (int mt = 0; mt < 4; mt++) {
        #pragma unroll
        for (int nt = 0; nt < 4; nt++) {
            int c = bn * 128 + wn * 32 + nt * 8 + lc2;
            #pragma unroll
            for (int half = 0; half < 2; half++) {
                int r = bm * 128 + wm * 64 + mt * 16 + lr4 + half * 8;
                float v0 = acc[mt][nt][half * 2 + 0];
                float v1 = acc[mt][nt][half * 2 + 1];
                long off = (long)r * N + c;
                if (EPI == 0) {
                    *(float2*)(C + off) = make_float2(v0, v1);
                } else if (EPI == 2) {
                    float2 bv = *(const float2*)(bias + c);
                    float2 rv = *(const float2*)(res + off);
                    *(float2*)(C + off) = make_float2(v0 + bv.x + rv.x,
                                                      v1 + bv.y + rv.y);
                } else {  // EPI == 3: bias + relu -> split bf16
                    float2 bv = *(const float2*)(bias + c);
                    v0 = fmaxf(v0 + bv.x, 0.f);
                    v1 = fmaxf(v1 + bv.y, 0.f);
                    __nv_bfloat16 h0,l0,h1,l1;
                    split_bf16(v0, h0, l0);
                    split_bf16(v1, h1, l1);
                    *(__nv_bfloat162*)(Chi + off) = __nv_bfloat162(h0, h1);
                    *(__nv_bfloat162*)(Clo + off) = __nv_bfloat162(l0, l1);
                }
            }
        }
    }
}

// ---------------------------------------------------------------------------
// Flash attention (fp32, online softmax) -> split bf16 output
// ---------------------------------------------------------------------------
__global__ void flash_kernel(const float* __restrict__ qkv,
                             __nv_bfloat16* __restrict__ out_hi,
                             __nv_bfloat16* __restrict__ out_lo)
{
    extern __shared__ float sm[];
    float* Qs = sm;               // 64 x 68
    float* KP = sm + 64 * 68;     // 64 x 68 (K tile, then P)
    float* Vs = sm + 2 * 64 * 68; // 64 x 64

    const int qi  = blockIdx.x;
    const int bh  = blockIdx.y;
    const int b   = bh >> 4;
    const int h   = bh & 15;
    const int tid = threadIdx.x;
    const int tr  = tid >> 4;
    const int tc  = tid & 15;
    const int lr  = tid >> 2;
    const int lc  = (tid & 3) << 4;

    const float* base = qkv + (long)b * Tq * (3 * Dq) + h * HDq;

    {
        const float* src = base + (long)(qi * 64 + lr) * (3 * Dq) + lc;
        #pragma unroll
        for (int u = 0; u < 4; u++) {
            float4 v = *(const float4*)(src + u * 4);
            v.x *= ATT_SCALE; v.y *= ATT_SCALE; v.z *= ATT_SCALE; v.w *= ATT_SCALE;
            *(float4*)(Qs + lr * 68 + lc + u * 4) = v;
        }
    }

    float m[4], l[4], o[4][4];
    #pragma unroll
    for (int i = 0; i < 4; i++) {
        m[i] = -1e30f; l[i] = 0.f;
        #pragma unroll
        for (int j = 0; j < 4; j++) o[i][j] = 0.f;
    }

    for (int jt = 0; jt <= qi; jt++) {
        __syncthreads();
        {
            const float* ks = base + (long)(jt * 64 + lr) * (3 * Dq) + Dq + lc;
            #pragma unroll
            for (int u = 0; u < 4; u++) {
                *(float4*)(KP + lr * 68 + lc + u * 4) = *(const float4*)(ks + u * 4);
                *(float4*)(Vs + lr * 64 + lc + u * 4) = *(const float4*)(ks + Dq + u * 4);
            }
        }
        __syncthreads();

        float s[4][4];
        #pragma unroll
        for (int i = 0; i < 4; i++)
            #pragma unroll
            for (int j = 0; j < 4; j++) s[i][j] = 0.f;
        #pragma unroll 4
        for (int k = 0; k < 64; k += 4) {
            float4 qv[4], kv[4];
            #pragma unroll
            for (int i = 0; i < 4; i++) qv[i] = *(const float4*)(Qs + (tr * 4 + i) * 68 + k);
            #pragma unroll
            for (int j = 0; j < 4; j++) kv[j] = *(const float4*)(KP + (tc * 4 + j) * 68 + k);
            #pragma unroll
            for (int i = 0; i < 4; i++)
                #pragma unroll
                for (int j = 0; j < 4; j++)
                    s[i][j] += qv[i].x * kv[j].x + qv[i].y * kv[j].y
                             + qv[i].z * kv[j].z + qv[i].w * kv[j].w;
        }

        if (jt == qi) {
            #pragma unroll
            for (int i = 0; i < 4; i++)
                #pragma unroll
                for (int j = 0; j < 4; j++)
                    if (tc * 4 + j > tr * 4 + i) s[i][j] = -1e30f;
        }

        float alpha[4];
        #pragma unroll
        for (int i = 0; i < 4; i++) {
            float mx = fmaxf(fmaxf(s[i][0], s[i][1]), fmaxf(s[i][2], s[i][3]));
            #pragma unroll
            for (int off = 8; off >= 1; off >>= 1)
                mx = fmaxf(mx, __shfl_xor_sync(0xffffffffu, mx, off));
            float mn = fmaxf(m[i], mx);
            alpha[i] = __expf(m[i] - mn);
            m[i] = mn;
            float rs = 0.f;
            #pragma unroll
            for (int j = 0; j < 4; j++) { s[i][j] = __expf(s[i][j] - mn); rs += s[i][j]; }
            #pragma unroll
            for (int off = 8; off >= 1; off >>= 1)
                rs += __shfl_xor_sync(0xffffffffu, rs, off);
            l[i] = l[i] * alpha[i] + rs;
            #pragma unroll
            for (int j = 0; j < 4; j++) o[i][j] *= alpha[i];
        }

        __syncthreads();
        #pragma unroll
        for (int i = 0; i < 4; i++)
            #pragma unroll
            for (int j = 0; j < 4; j++)
                KP[(tr * 4 + i) * 68 + tc * 4 + j] = s[i][j];
        __syncthreads();

        #pragma unroll 4
        for (int c = 0; c < 64; c++) {
            float4 v4 = *(const float4*)(Vs + c * 64 + tc * 4);
            #pragma unroll
            for (int i = 0; i < 4; i++) {
                float p = KP[(tr * 4 + i) * 68 + c];
                o[i][0] += p * v4.x; o[i][1] += p * v4.y;
                o[i][2] += p * v4.z; o[i][3] += p * v4.w;
            }
        }
    }

    #pragma unroll
    for (int i = 0; i < 4; i++) {
        float inv = 1.f / l[i];
        long off = (long)(b * Tq + qi * 64 + tr * 4 + i) * Dq + h * HDq + tc * 4;
        __nv_bfloat16 h0,l0,h1,l1,h2,l2,h3,l3;
        split_bf16(o[i][0] * inv, h0, l0);
        split_bf16(o[i][1] * inv, h1, l1);
        split_bf16(o[i][2] * inv, h2, l2);
        split_bf16(o[i][3] * inv, h3, l3);
        *(__nv_bfloat162*)(out_hi + off)     = __nv_bfloat162(h0, h1);
        *(__nv_bfloat162*)(out_hi + off + 2) = __nv_bfloat162(h2, h3);
        *(__nv_bfloat162*)(out_lo + off)     = __nv_bfloat162(l0, l1);
        *(__nv_bfloat162*)(out_lo + off + 2) = __nv_bfloat162(l2, l3);
    }
}

// ---------------------------------------------------------------------------
// Launch
// ---------------------------------------------------------------------------
extern "C" void kernel_launch(void* const* d_in, const int* in_sizes, int n_in,
                              void* d_out, int out_size)
{
    const float* x   = (const float*)d_in[0];
    const float* Wq  = (const float*)d_in[1];
    const float* Wk  = (const float*)d_in[2];
    const float* Wv  = (const float*)d_in[3];
    const float* Wp  = (const float*)d_in[4];
    const float* bp  = (const float*)d_in[5];
    const float* W1  = (const float*)d_in[6];
    const float* b1  = (const float*)d_in[7];
    const float* W2  = (const float*)d_in[8];
    const float* b2  = (const float*)d_in[9];
    const float* g1  = (const float*)d_in[10];
    const float* be1 = (const float*)d_in[11];
    const float* g2  = (const float*)d_in[12];
    const float* be2 = (const float*)d_in[13];
    float* out = (float*)d_out;

    __nv_bfloat16 *p_h_hi, *p_h_lo, *p_wqkv_hi, *p_wqkv_lo, *p_wp_hi, *p_wp_lo;
    __nv_bfloat16 *p_w1_hi, *p_w1_lo, *p_w2_hi, *p_w2_lo;
    __nv_bfloat16 *p_attn_hi, *p_attn_lo, *p_ff_hi, *p_ff_lo;
    float *p_qkv, *p_x1;
    cudaGetSymbolAddress((void**)&p_h_hi,    g_h_hi);
    cudaGetSymbolAddress((void**)&p_h_lo,    g_h_lo);
    cudaGetSymbolAddress((void**)&p_wqkv_hi, g_wqkv_hi);
    cudaGetSymbolAddress((void**)&p_wqkv_lo, g_wqkv_lo);
    cudaGetSymbolAddress((void**)&p_wp_hi,   g_wp_hi);
    cudaGetSymbolAddress((void**)&p_wp_lo,   g_wp_lo);
    cudaGetSymbolAddress((void**)&p_w1_hi,   g_w1_hi);
    cudaGetSymbolAddress((void**)&p_w1_lo,   g_w1_lo);
    cudaGetSymbolAddress((void**)&p_w2_hi,   g_w2_hi);
    cudaGetSymbolAddress((void**)&p_w2_lo,   g_w2_lo);
    cudaGetSymbolAddress((void**)&p_qkv,     g_qkv);
    cudaGetSymbolAddress((void**)&p_attn_hi, g_attn_hi);
    cudaGetSymbolAddress((void**)&p_attn_lo, g_attn_lo);
    cudaGetSymbolAddress((void**)&p_x1,      g_x1);
    cudaGetSymbolAddress((void**)&p_ff_hi,   g_ff_hi);
    cudaGetSymbolAddress((void**)&p_ff_lo,   g_ff_lo);

    const int gemm_smem  = 2 * 2 * 2 * 128 * KPAD * (int)sizeof(__nv_bfloat16); // 81920
    const int flash_smem = (2 * 64 * 68 + 64 * 64) * (int)sizeof(float);        // 51200
    cudaFuncSetAttribute(gemm_bf16x3<0>, cudaFuncAttributeMaxDynamicSharedMemorySize, gemm_smem);
    cudaFuncSetAttribute(gemm_bf16x3<2>, cudaFuncAttributeMaxDynamicSharedMemorySize, gemm_smem);
    cudaFuncSetAttribute(gemm_bf16x3<3>, cudaFuncAttributeMaxDynamicSharedMemorySize, gemm_smem);
    cudaFuncSetAttribute(flash_kernel,   cudaFuncAttributeMaxDynamicSharedMemorySize, flash_smem);

    // weight prep (split + transpose to [N][K])
    prep_wqkv_t<<<(3 * Dq * Dq + 255) / 256, 256>>>(Wq, Wk, Wv, p_wqkv_hi, p_wqkv_lo);
    transpose_split<<<(Dq * Dq + 255) / 256, 256>>>(Wp, p_wp_hi, p_wp_lo, Dq, Dq);
    transpose_split<<<(Dq * DFF + 255) / 256, 256>>>(W1, p_w1_hi, p_w1_lo, Dq, DFF);
    transpose_split<<<(DFF * Dq + 255) / 256, 256>>>(W2, p_w2_hi, p_w2_lo, DFF, Dq);

    // LN1 -> split bf16
    ln_split_kernel<<<Mq, 256>>>(x, g1, be1, p_h_hi, p_h_lo);
    // QKV projection: [8192,1024] @ [1024,3072] -> fp32
    gemm_bf16x3<0><<<dim3(3 * Dq / 128, Mq / 128), 256, gemm_smem>>>(
        p_h_hi, p_h_lo, p_wqkv_hi, p_wqkv_lo, nullptr, nullptr,
        p_qkv, nullptr, nullptr, 3 * Dq, Dq);
    // flash attention -> split bf16
    flash_kernel<<<dim3(Tq / 64, Bq * Hq), 256, flash_smem>>>(p_qkv, p_attn_hi, p_attn_lo);
    // output projection + bias + residual(x) -> x1 fp32
    gemm_bf16x3<2><<<dim3(Dq / 128, Mq / 128), 256, gemm_smem>>>(
        p_attn_hi, p_attn_lo, p_wp_hi, p_wp_lo, bp, x,
        p_x1, nullptr, nullptr, Dq, Dq);
    // LN2 -> split bf16
    ln_split_kernel<<<Mq, 256>>>(p_x1, g2, be2, p_h_hi, p_h_lo);
    // FFN up + bias + relu -> split bf16
    gemm_bf16x3<3><<<dim3(DFF / 128, Mq / 128), 256, gemm_smem>>>(
        p_h_hi, p_h_lo, p_w1_hi, p_w1_lo, b1, nullptr,
        nullptr, p_ff_hi, p_ff_lo, DFF, Dq);
    // FFN down + bias + residual(x1) -> d_out fp32
    gemm_bf16x3<2><<<dim3(Dq / 128, Mq / 128), 256, gemm_smem>>>(
        p_ff_hi, p_ff_lo, p_w2_hi, p_w2_lo, b2, p_x1,
        out, nullptr, nullptr, Dq, DFF);
}

// round 3
// speedup vs baseline: 2.8765x; 1.6698x over previous
#include <cuda_runtime.h>
#include <cuda_bf16.h>
#include <stdint.h>

// Problem constants
#define Bq   4
#define Tq   2048
#define Dq   1024
#define Hq   16
#define HDq  64
#define Mq   (Bq * Tq)        // 8192 rows
#define DFF  (4 * Dq)         // 4096
#define LN_EPS 1e-5f
#define ATT_SCALE 0.125f      // HD^-0.5

// ---------------------------------------------------------------------------
// Scratch (static device globals: allocation-free, graph-capture safe)
// ---------------------------------------------------------------------------
__device__ __nv_bfloat16 g_h_hi[Mq * Dq],    g_h_lo[Mq * Dq];        // LN out (split)
__device__ __nv_bfloat16 g_wqkv_hi[3*Dq*Dq], g_wqkv_lo[3*Dq*Dq];     // [3D][D] (N-major)
__device__ __nv_bfloat16 g_wp_hi[Dq*Dq],     g_wp_lo[Dq*Dq];         // [D][D] transposed
__device__ __nv_bfloat16 g_w1_hi[Dq*DFF],    g_w1_lo[Dq*DFF];        // [4D][D] transposed
__device__ __nv_bfloat16 g_w2_hi[DFF*Dq],    g_w2_lo[DFF*Dq];        // [D][4D] transposed
__device__ __nv_bfloat16 g_qkvh[Mq * 3 * Dq], g_qkvl[Mq * 3 * Dq];   // QKV split bf16 (q pre-scaled)
__device__ __nv_bfloat16 g_attn_hi[Mq * Dq], g_attn_lo[Mq * Dq];     // attn out (split)
__device__ float         g_x1[Mq * Dq];                               // residual-1
__device__ __nv_bfloat16 g_ff_hi[Mq * DFF],  g_ff_lo[Mq * DFF];      // FFN hidden (split)

// ---------------------------------------------------------------------------
// Helpers
// ---------------------------------------------------------------------------
__device__ __forceinline__ void split_bf16(float v, __nv_bfloat16& hi, __nv_bfloat16& lo) {
    hi = __float2bfloat16(v);
    lo = __float2bfloat16(v - __bfloat162float(hi));
}

// pack two floats into bf16x2 hi word, residuals into lo word
__device__ __forceinline__ uint32_t pack2(float x, float y, uint32_t& lo) {
    __nv_bfloat16 hx = __float2bfloat16(x), hy = __float2bfloat16(y);
    __nv_bfloat16 lx = __float2bfloat16(x - __bfloat162float(hx));
    __nv_bfloat16 ly = __float2bfloat16(y - __bfloat162float(hy));
    __nv_bfloat162 h2(hx, hy), l2(lx, ly);
    lo = *reinterpret_cast<uint32_t*>(&l2);
    return *reinterpret_cast<uint32_t*>(&h2);
}

__device__ __forceinline__ void mma16816(float* c, const uint32_t* a, const uint32_t* b) {
    asm volatile(
        "mma.sync.aligned.m16n8k16.row.col.f32.bf16.bf16.f32 "
        "{%0,%1,%2,%3}, {%4,%5,%6,%7}, {%8,%9}, {%0,%1,%2,%3};"
        : "+f"(c[0]), "+f"(c[1]), "+f"(c[2]), "+f"(c[3])
        : "r"(a[0]), "r"(a[1]), "r"(a[2]), "r"(a[3]), "r"(b[0]), "r"(b[1]));
}

__device__ __forceinline__ void ldmx2t(uint32_t& r0, uint32_t& r1, const void* p) {
    uint32_t a = (uint32_t)__cvta_generic_to_shared(p);
    asm volatile("ldmatrix.sync.aligned.m8n8.x2.trans.shared.b16 {%0,%1}, [%2];"
                 : "=r"(r0), "=r"(r1) : "r"(a));
}

__device__ __forceinline__ void cp16(void* sdst, const void* gsrc) {
    unsigned sa = (unsigned)__cvta_generic_to_shared(sdst);
    asm volatile("cp.async.cg.shared.global [%0], [%1], 16;" :: "r"(sa), "l"(gsrc));
}
#define CP_COMMIT() asm volatile("cp.async.commit_group;")
#define CP_WAIT0()  asm volatile("cp.async.wait_group 0;")

// ---------------------------------------------------------------------------
// Weight prep
// ---------------------------------------------------------------------------
__global__ void prep_wqkv_t(const float* __restrict__ Wq,
                            const float* __restrict__ Wk,
                            const float* __restrict__ Wv,
                            __nv_bfloat16* __restrict__ o_hi,
                            __nv_bfloat16* __restrict__ o_lo)
{
    int i = blockIdx.x * blockDim.x + threadIdx.x;
    if (i >= 3 * Dq * Dq) return;
    int n = i / Dq;
    int d = i % Dq;
    int s = n >> 10;
    int hc = n & 1023;
    int h = hc >> 6, hd = hc & 63;
    const float* W = (s == 0) ? Wq : (s == 1) ? Wk : Wv;
    float v = W[((long)h * Dq + d) * HDq + hd];
    split_bf16(v, o_hi[i], o_lo[i]);
}

__global__ void transpose_split(const float* __restrict__ in,
                                __nv_bfloat16* __restrict__ o_hi,
                                __nv_bfloat16* __restrict__ o_lo,
                                int K, int N)
{
    long i = (long)blockIdx.x * blockDim.x + threadIdx.x;
    if (i >= (long)K * N) return;
    int n = (int)(i / K);
    int k = (int)(i % K);
    float v = in[(long)k * N + n];
    split_bf16(v, o_hi[i], o_lo[i]);
}

// ---------------------------------------------------------------------------
// LayerNorm -> split bf16
// ---------------------------------------------------------------------------
__global__ void ln_split_kernel(const float* __restrict__ x,
                                const float* __restrict__ g,
                                const float* __restrict__ b,
                                __nv_bfloat16* __restrict__ o_hi,
                                __nv_bfloat16* __restrict__ o_lo)
{
    __shared__ float red[16];
    int row = blockIdx.x;
    int t = threadIdx.x;
    const float4* xr = (const float4*)(x + (long)row * Dq);
    float4 v = xr[t];
    float s  = v.x + v.y + v.z + v.w;
    float ss = v.x * v.x + v.y * v.y + v.z * v.z + v.w * v.w;
    #pragma unroll
    for (int o = 16; o >= 1; o >>= 1) {
        s  += __shfl_xor_sync(0xffffffffu, s,  o);
        ss += __shfl_xor_sync(0xffffffffu, ss, o);
    }
    if ((t & 31) == 0) { red[t >> 5] = s; red[8 + (t >> 5)] = ss; }
    __syncthreads();
    float stot = 0.f, sstot = 0.f;
    #pragma unroll
    for (int w = 0; w < 8; w++) { stot += red[w]; sstot += red[8 + w]; }
    float mu  = stot * (1.f / Dq);
    float var = sstot * (1.f / Dq) - mu * mu;
    float inv = rsqrtf(var + LN_EPS);
    float4 gg = ((const float4*)g)[t];
    float4 bb = ((const float4*)b)[t];
    float o0 = (v.x - mu) * inv * gg.x + bb.x;
    float o1 = (v.y - mu) * inv * gg.y + bb.y;
    float o2 = (v.z - mu) * inv * gg.z + bb.z;
    float o3 = (v.w - mu) * inv * gg.w + bb.w;
    __nv_bfloat16 h0,l0,h1,l1,h2,l2,h3,l3;
    split_bf16(o0,h0,l0); split_bf16(o1,h1,l1);
    split_bf16(o2,h2,l2); split_bf16(o3,h3,l3);
    long base = (long)row * Dq + t * 4;
    *(__nv_bfloat162*)(o_hi + base)     = __nv_bfloat162(h0, h1);
    *(__nv_bfloat162*)(o_hi + base + 2) = __nv_bfloat162(h2, h3);
    *(__nv_bfloat162*)(o_lo + base)     = __nv_bfloat162(l0, l1);
    *(__nv_bfloat162*)(o_lo + base + 2) = __nv_bfloat162(l2, l3);
}

// ---------------------------------------------------------------------------
// bf16x3 tensor-core GEMM (same as R2).
// EPI: 0 fp32 out; 2 +bias+residual fp32; 3 +bias+relu -> split bf16;
//      4 -> split bf16 with q-region prescale (QKV output)
// ---------------------------------------------------------------------------
#define KPAD 40
#define TILE_E (128 * KPAD)

template <int EPI>
__global__ void __launch_bounds__(256)
gemm_bf16x3(const __nv_bfloat16* __restrict__ Ahi,
            const __nv_bfloat16* __restrict__ Alo,
            const __nv_bfloat16* __restrict__ Bhi,
            const __nv_bfloat16* __restrict__ Blo,
            const float* __restrict__ bias,
            const float* __restrict__ res,
            float* __restrict__ C,
            __nv_bfloat16* __restrict__ Chi,
            __nv_bfloat16* __restrict__ Clo,
            int N, int K)
{
    extern __shared__ __nv_bfloat16 smem[];
    const int tid  = threadIdx.x;
    const int lane = tid & 31;
    const int warp = tid >> 5;
    const int wm = warp >> 2;
    const int wn = warp & 3;
    const int fr = lane >> 2;
    const int fc = (lane & 3) * 2;

    const int bm = blockIdx.y, bn = blockIdx.x;
    const __nv_bfloat16* Ahi_b = Ahi + (long)bm * 128 * K;
    const __nv_bfloat16* Alo_b = Alo + (long)bm * 128 * K;
    const __nv_bfloat16* Bhi_b = Bhi + (long)bn * 128 * K;
    const __nv_bfloat16* Blo_b = Blo + (long)bn * 128 * K;

    const int r0  = tid >> 2;
    const int seg = (tid & 3) * 8;

    auto sbase = [&](int st, int ab, int p) -> __nv_bfloat16* {
        return smem + (((st * 2) + ab) * 2 + p) * TILE_E;
    };

    auto ld_tile = [&](int st, int kt) {
        long k0 = (long)kt * 32;
        #pragma unroll
        for (int rr = 0; rr < 2; rr++) {
            int r = r0 + rr * 64;
            long go = (long)r * K + k0 + seg;
            int  so = r * KPAD + seg;
            cp16(sbase(st,0,0) + so, Ahi_b + go);
            cp16(sbase(st,0,1) + so, Alo_b + go);
            cp16(sbase(st,1,0) + so, Bhi_b + go);
            cp16(sbase(st,1,1) + so, Blo_b + go);
        }
    };

    float acc[4][4][4];
    #pragma unroll
    for (int i = 0; i < 4; i++)
        #pragma unroll
        for (int j = 0; j < 4; j++)
            #pragma unroll
            for (int r = 0; r < 4; r++) acc[i][j][r] = 0.f;

    const int KT = K / 32;
    ld_tile(0, 0);
    CP_COMMIT();

    for (int kt = 0; kt < KT; kt++) {
        CP_WAIT0();
        __syncthreads();
        if (kt + 1 < KT) {
            ld_tile((kt + 1) & 1, kt + 1);
            CP_COMMIT();
        }
        const int st = kt & 1;
        const __nv_bfloat16* sAh = sbase(st, 0, 0);
        const __nv_bfloat16* sAl = sbase(st, 0, 1);
        const __nv_bfloat16* sBh = sbase(st, 1, 0);
        const __nv_bfloat16* sBl = sbase(st, 1, 1);

        #pragma unroll
        for (int ks = 0; ks < 2; ks++) {
            uint32_t ah[4][4], al[4][4], bh[4][2], bl[4][2];
            #pragma unroll
            for (int mt = 0; mt < 4; mt++) {
                int row = wm * 64 + mt * 16 + fr;
                int col = ks * 16 + fc;
                const __nv_bfloat16* pa = sAh + row * KPAD + col;
                const __nv_bfloat16* pl = sAl + row * KPAD + col;
                ah[mt][0] = *(const uint32_t*)pa;
                ah[mt][1] = *(const uint32_t*)(pa + 8 * KPAD);
                ah[mt][2] = *(const uint32_t*)(pa + 8);
                ah[mt][3] = *(const uint32_t*)(pa + 8 * KPAD + 8);
                al[mt][0] = *(const uint32_t*)pl;
                al[mt][1] = *(const uint32_t*)(pl + 8 * KPAD);
                al[mt][2] = *(const uint32_t*)(pl + 8);
                al[mt][3] = *(const uint32_t*)(pl + 8 * KPAD + 8);
            }
            #pragma unroll
            for (int nt = 0; nt < 4; nt++) {
                int n = wn * 32 + nt * 8 + fr;
                int k = ks * 16 + fc;
                const __nv_bfloat16* pb = sBh + n * KPAD + k;
                const __nv_bfloat16* pq = sBl + n * KPAD + k;
                bh[nt][0] = *(const uint32_t*)pb;
                bh[nt][1] = *(const uint32_t*)(pb + 8);
                bl[nt][0] = *(const uint32_t*)pq;
                bl[nt][1] = *(const uint32_t*)(pq + 8);
            }
            #pragma unroll
            for (int mt = 0; mt < 4; mt++)
                #pragma unroll
                for (int nt = 0; nt < 4; nt++) {
                    mma16816(acc[mt][nt], ah[mt], bh[nt]);
                    mma16816(acc[mt][nt], ah[mt], bl[nt]);
                    mma16816(acc[mt][nt], al[mt], bh[nt]);
                }
        }
        __syncthreads();
    }

    const int lr4 = lane >> 2;
    const int lc2 = (lane & 3) * 2;
    #pragma unroll
    for (int mt = 0; mt < 4; mt++) {
        #pragma unroll
        for (int nt = 0; nt < 4; nt++) {
            int c = bn * 128 + wn * 32 + nt * 8 + lc2;
            #pragma unroll
            for (int half = 0; half < 2; half++) {
                int r = bm * 128 + wm * 64 + mt * 16 + lr4 + half * 8;
                float v0 = acc[mt][nt][half * 2 + 0];
                float v1 = acc[mt][nt][half * 2 + 1];
                long off = (long)r * N + c;
                if (EPI == 0) {
                    *(float2*)(C + off) = make_float2(v0, v1);
                } else if (EPI == 2) {
                    float2 bv = *(const float2*)(bias + c);
                    float2 rv = *(const float2*)(res + off);
                    *(float2*)(C + off) = make_float2(v0 + bv.x + rv.x,
                                                      v1 + bv.y + rv.y);
                } else if (EPI == 3) {
                    float2 bv = *(const float2*)(bias + c);
                    v0 = fmaxf(v0 + bv.x, 0.f);
                    v1 = fmaxf(v1 + bv.y, 0.f);
                    uint32_t lo;
                    uint32_t hi = pack2(v0, v1, lo);
                    *(uint32_t*)(Chi + off) = hi;
                    *(uint32_t*)(Clo + off) = lo;
                } else {  // EPI == 4: QKV split output, q cols pre-scaled
                    float scale = (c < Dq) ? ATT_SCALE : 1.f;
                    uint32_t lo;
                    uint32_t hi = pack2(v0 * scale, v1 * scale, lo);
                    *(uint32_t*)(Chi + off) = hi;
                    *(uint32_t*)(Clo + off) = lo;
                }
            }
        }
    }
}

// ---------------------------------------------------------------------------
// Tensor-core flash attention (bf16x3 QK^T and PV, FA2 register pipeline).
// Block: 128 Q rows x one (b,h). 8 warps x 16 rows. KV tile = 64 keys.
// Smem: Q hi/lo [128][72] + 2 stages of {K,V} hi/lo [64][72]. cp.async.
// ---------------------------------------------------------------------------
#define FPAD 72
#define FLASH_SMEM ((2 * 128 * FPAD + 2 * 4 * 64 * FPAD) * 2)   // 110592 B

__global__ void __launch_bounds__(256)
flash_tc(const __nv_bfloat16* __restrict__ qkvh,
         const __nv_bfloat16* __restrict__ qkvl,
         __nv_bfloat16* __restrict__ out_hi,
         __nv_bfloat16* __restrict__ out_lo)
{
    extern __shared__ __nv_bfloat16 sm[];
    __nv_bfloat16* QH = sm;
    __nv_bfloat16* QL = sm + 128 * FPAD;

    const int qi  = gridDim.x - 1 - blockIdx.x;   // heavy blocks first
    const int bh  = blockIdx.y;
    const int b   = bh >> 4;
    const int h   = bh & 15;
    const int tid  = threadIdx.x;
    const int lane = tid & 31;
    const int warp = tid >> 5;          // 0..7, rows warp*16..+15
    const int g  = lane >> 2;           // 0..7
    const int t2 = (lane & 3) * 2;      // 0,2,4,6

    const long rb = (long)b * Tq;
    const __nv_bfloat16* qh = qkvh + (rb + qi * 128) * (3 * Dq) + h * HDq;
    const __nv_bfloat16* ql = qkvl + (rb + qi * 128) * (3 * Dq) + h * HDq;
    const __nv_bfloat16* kh = qkvh + rb * (3 * Dq) + Dq + h * HDq;
    const __nv_bfloat16* kl = qkvl + rb * (3 * Dq) + Dq + h * HDq;
    const __nv_bfloat16* vh = qkvh + rb * (3 * Dq) + 2 * Dq + h * HDq;
    const __nv_bfloat16* vl = qkvl + rb * (3 * Dq) + 2 * Dq + h * HDq;

    auto kvbase = [&](int st) -> __nv_bfloat16* {
        return sm + 2 * 128 * FPAD + st * (4 * 64 * FPAD);
    };
    auto ldkv = [&](int st, int jt) {
        __nv_bfloat16* KB = kvbase(st);
        #pragma unroll
        for (int i = 0; i < 2; i++) {
            int c = tid + i * 256;
            int row = c >> 3;
            int c8 = (c & 7) * 8;
            long go = (long)(jt * 64 + row) * (3 * Dq) + c8;
            int so = row * FPAD + c8;
            cp16(KB + so,                 kh + go);
            cp16(KB + 64 * FPAD + so,     kl + go);
            cp16(KB + 2 * 64 * FPAD + so, vh + go);
            cp16(KB + 3 * 64 * FPAD + so, vl + go);
        }
    };

    // prologue: Q + first KV tile
    #pragma unroll
    for (int i = 0; i < 4; i++) {
        int c = tid + i * 256;
        int row = c >> 3;
        int c8 = (c & 7) * 8;
        cp16(QH + row * FPAD + c8, qh + (long)row * (3 * Dq) + c8);
        cp16(QL + row * FPAD + c8, ql + (long)row * (3 * Dq) + c8);
    }
    ldkv(0, 0);
    CP_COMMIT();

    float oacc[8][4];
    #pragma unroll
    for (int nt = 0; nt < 8; nt++)
        #pragma unroll
        for (int e = 0; e < 4; e++) oacc[nt][e] = 0.f;
    float m0 = -1e30f, m1 = -1e30f, l0 = 0.f, l1 = 0.f;

    const int qrow0 = qi * 128 + warp * 16 + g;   // absolute q row (c0/c1)
    const int jmax = 2 * qi + 1;

    for (int jt = 0; jt <= jmax; jt++) {
        CP_WAIT0();
        __syncthreads();
        if (jt < jmax) { ldkv((jt + 1) & 1, jt + 1); CP_COMMIT(); }

        // skip tiles fully above the causal diagonal for this warp
        if (jt * 64 <= qi * 128 + warp * 16 + 15) {
            __nv_bfloat16* KB = kvbase(jt & 1);
            const __nv_bfloat16* KHs = KB;
            const __nv_bfloat16* KLs = KB + 64 * FPAD;
            const __nv_bfloat16* VHs = KB + 2 * 64 * FPAD;
            const __nv_bfloat16* VLs = KB + 3 * 64 * FPAD;

            // ---- S = Q K^T (3-term bf16) ----
            float sacc[8][4];
            #pragma unroll
            for (int nt = 0; nt < 8; nt++)
                #pragma unroll
                for (int e = 0; e < 4; e++) sacc[nt][e] = 0.f;

            #pragma unroll
            for (int kt = 0; kt < 4; kt++) {
                uint32_t ah[4], al[4];
                const __nv_bfloat16* pa = QH + (warp * 16 + g) * FPAD + kt * 16 + t2;
                const __nv_bfloat16* pl = QL + (warp * 16 + g) * FPAD + kt * 16 + t2;
                ah[0] = *(const uint32_t*)pa;
                ah[1] = *(const uint32_t*)(pa + 8 * FPAD);
                ah[2] = *(const uint32_t*)(pa + 8);
                ah[3] = *(const uint32_t*)(pa + 8 * FPAD + 8);
                al[0] = *(const uint32_t*)pl;
                al[1] = *(const uint32_t*)(pl + 8 * FPAD);
                al[2] = *(const uint32_t*)(pl + 8);
                al[3] = *(const uint32_t*)(pl + 8 * FPAD + 8);
                #pragma unroll
                for (int nt = 0; nt < 8; nt++) {
                    const __nv_bfloat16* pb = KHs + (nt * 8 + g) * FPAD + kt * 16 + t2;
                    const __nv_bfloat16* pq = KLs + (nt * 8 + g) * FPAD + kt * 16 + t2;
                    uint32_t bhf[2] = { *(const uint32_t*)pb, *(const uint32_t*)(pb + 8) };
                    uint32_t blf[2] = { *(const uint32_t*)pq, *(const uint32_t*)(pq + 8) };
                    mma16816(sacc[nt], ah, bhf);
                    mma16816(sacc[nt], ah, blf);
                    mma16816(sacc[nt], al, bhf);
                }
            }

            // ---- causal mask ----
            if (jt * 64 + 63 > qrow0) {
                #pragma unroll
                for (int nt = 0; nt < 8; nt++) {
                    int key0 = jt * 64 + nt * 8 + t2;
                    if (key0     > qrow0)     sacc[nt][0] = -1e30f;
                    if (key0 + 1 > qrow0)     sacc[nt][1] = -1e30f;
                    if (key0     > qrow0 + 8) sacc[nt][2] = -1e30f;
                    if (key0 + 1 > qrow0 + 8) sacc[nt][3] = -1e30f;
                }
            }

            // ---- online softmax ----
            float mx0 = -1e30f, mx1 = -1e30f;
            #pragma unroll
            for (int nt = 0; nt < 8; nt++) {
                mx0 = fmaxf(mx0, fmaxf(sacc[nt][0], sacc[nt][1]));
                mx1 = fmaxf(mx1, fmaxf(sacc[nt][2], sacc[nt][3]));
            }
            mx0 = fmaxf(mx0, __shfl_xor_sync(0xffffffffu, mx0, 1));
            mx0 = fmaxf(mx0, __shfl_xor_sync(0xffffffffu, mx0, 2));
            mx1 = fmaxf(mx1, __shfl_xor_sync(0xffffffffu, mx1, 1));
            mx1 = fmaxf(mx1, __shfl_xor_sync(0xffffffffu, mx1, 2));
            float mn0 = fmaxf(m0, mx0), mn1 = fmaxf(m1, mx1);
            float a0 = __expf(m0 - mn0), a1 = __expf(m1 - mn1);
            m0 = mn0; m1 = mn1;
            float rs0 = 0.f, rs1 = 0.f;
            #pragma unroll
            for (int nt = 0; nt < 8; nt++) {
                sacc[nt][0] = __expf(sacc[nt][0] - mn0); rs0 += sacc[nt][0];
                sacc[nt][1] = __expf(sacc[nt][1] - mn0); rs0 += sacc[nt][1];
                sacc[nt][2] = __expf(sacc[nt][2] - mn1); rs1 += sacc[nt][2];
                sacc[nt][3] = __expf(sacc[nt][3] - mn1); rs1 += sacc[nt][3];
            }
            rs0 += __shfl_xor_sync(0xffffffffu, rs0, 1);
            rs0 += __shfl_xor_sync(0xffffffffu, rs0, 2);
            rs1 += __shfl_xor_sync(0xffffffffu, rs1, 1);
            rs1 += __shfl_xor_sync(0xffffffffu, rs1, 2);
            l0 = l0 * a0 + rs0;
            l1 = l1 * a1 + rs1;
            #pragma unroll
            for (int nt = 0; nt < 8; nt++) {
                oacc[nt][0] *= a0; oacc[nt][1] *= a0;
                oacc[nt][2] *= a1; oacc[nt][3] *= a1;
            }

            // ---- O += P V  (P from registers, V via ldmatrix.trans) ----
            #pragma unroll
            for (int j = 0; j < 4; j++) {
                uint32_t ph[4], pl4[4];
                ph[0] = pack2(sacc[2*j][0],   sacc[2*j][1],   pl4[0]);
                ph[1] = pack2(sacc[2*j][2],   sacc[2*j][3],   pl4[1]);
                ph[2] = pack2(sacc[2*j+1][0], sacc[2*j+1][1], pl4[2]);
                ph[3] = pack2(sacc[2*j+1][2], sacc[2*j+1][3], pl4[3]);
                #pragma unroll
                for (int nt = 0; nt < 8; nt++) {
                    uint32_t vhf[2], vlf[2];
                    ldmx2t(vhf[0], vhf[1], VHs + (j * 16 + (lane & 15)) * FPAD + nt * 8);
                    ldmx2t(vlf[0], vlf[1], VLs + (j * 16 + (lane & 15)) * FPAD + nt * 8);
                    mma16816(oacc[nt], ph, vhf);
                    mma16816(oacc[nt], ph, vlf);
                    mma16816(oacc[nt], pl4, vhf);
                }
            }
        }
        __syncthreads();
    }

    // ---- finalize + split-bf16 store ----
    float inv0 = 1.f / l0, inv1 = 1.f / l1;
    long row0 = (long)b * Tq + qi * 128 + warp * 16 + g;
    #pragma unroll
    for (int nt = 0; nt < 8; nt++) {
        int col = h * HDq + nt * 8 + t2;
        uint32_t lo;
        uint32_t hi = pack2(oacc[nt][0] * inv0, oacc[nt][1] * inv0, lo);
        *(uint32_t*)(out_hi + row0 * Dq + col) = hi;
        *(uint32_t*)(out_lo + row0 * Dq + col) = lo;
        hi = pack2(oacc[nt][2] * inv1, oacc[nt][3] * inv1, lo);
        *(uint32_t*)(out_hi + (row0 + 8) * Dq + col) = hi;
        *(uint32_t*)(out_lo + (row0 + 8) * Dq + col) = lo;
    }
}

// ---------------------------------------------------------------------------
// Launch
// ---------------------------------------------------------------------------
extern "C" void kernel_launch(void* const* d_in, const int* in_sizes, int n_in,
                              void* d_out, int out_size)
{
    const float* x   = (const float*)d_in[0];
    const float* Wq  = (const float*)d_in[1];
    const float* Wk  = (const float*)d_in[2];
    const float* Wv  = (const float*)d_in[3];
    const float* Wp  = (const float*)d_in[4];
    const float* bp  = (const float*)d_in[5];
    const float* W1  = (const float*)d_in[6];
    const float* b1  = (const float*)d_in[7];
    const float* W2  = (const float*)d_in[8];
    const float* b2  = (const float*)d_in[9];
    const float* g1  = (const float*)d_in[10];
    const float* be1 = (const float*)d_in[11];
    const float* g2  = (const float*)d_in[12];
    const float* be2 = (const float*)d_in[13];
    float* out = (float*)d_out;

    __nv_bfloat16 *p_h_hi, *p_h_lo, *p_wqkv_hi, *p_wqkv_lo, *p_wp_hi, *p_wp_lo;
    __nv_bfloat16 *p_w1_hi, *p_w1_lo, *p_w2_hi, *p_w2_lo;
    __nv_bfloat16 *p_attn_hi, *p_attn_lo, *p_ff_hi, *p_ff_lo, *p_qkvh, *p_qkvl;
    float *p_x1;
    cudaGetSymbolAddress((void**)&p_h_hi,    g_h_hi);
    cudaGetSymbolAddress((void**)&p_h_lo,    g_h_lo);
    cudaGetSymbolAddress((void**)&p_wqkv_hi, g_wqkv_hi);
    cudaGetSymbolAddress((void**)&p_wqkv_lo, g_wqkv_lo);
    cudaGetSymbolAddress((void**)&p_wp_hi,   g_wp_hi);
    cudaGetSymbolAddress((void**)&p_wp_lo,   g_wp_lo);
    cudaGetSymbolAddress((void**)&p_w1_hi,   g_w1_hi);
    cudaGetSymbolAddress((void**)&p_w1_lo,   g_w1_lo);
    cudaGetSymbolAddress((void**)&p_w2_hi,   g_w2_hi);
    cudaGetSymbolAddress((void**)&p_w2_lo,   g_w2_lo);
    cudaGetSymbolAddress((void**)&p_qkvh,    g_qkvh);
    cudaGetSymbolAddress((void**)&p_qkvl,    g_qkvl);
    cudaGetSymbolAddress((void**)&p_attn_hi, g_attn_hi);
    cudaGetSymbolAddress((void**)&p_attn_lo, g_attn_lo);
    cudaGetSymbolAddress((void**)&p_x1,      g_x1);
    cudaGetSymbolAddress((void**)&p_ff_hi,   g_ff_hi);
    cudaGetSymbolAddress((void**)&p_ff_lo,   g_ff_lo);

    const int gemm_smem = 2 * 2 * 2 * 128 * KPAD * (int)sizeof(__nv_bfloat16);
    cudaFuncSetAttribute(gemm_bf16x3<0>, cudaFuncAttributeMaxDynamicSharedMemorySize, gemm_smem);
    cudaFuncSetAttribute(gemm_bf16x3<2>, cudaFuncAttributeMaxDynamicSharedMemorySize, gemm_smem);
    cudaFuncSetAttribute(gemm_bf16x3<3>, cudaFuncAttributeMaxDynamicSharedMemorySize, gemm_smem);
    cudaFuncSetAttribute(gemm_bf16x3<4>, cudaFuncAttributeMaxDynamicSharedMemorySize, gemm_smem);
    cudaFuncSetAttribute(flash_tc,       cudaFuncAttributeMaxDynamicSharedMemorySize, FLASH_SMEM);

    // weight prep
    prep_wqkv_t<<<(3 * Dq * Dq + 255) / 256, 256>>>(Wq, Wk, Wv, p_wqkv_hi, p_wqkv_lo);
    transpose_split<<<(Dq * Dq + 255) / 256, 256>>>(Wp, p_wp_hi, p_wp_lo, Dq, Dq);
    transpose_split<<<(Dq * DFF + 255) / 256, 256>>>(W1, p_w1_hi, p_w1_lo, Dq, DFF);
    transpose_split<<<(DFF * Dq + 255) / 256, 256>>>(W2, p_w2_hi, p_w2_lo, DFF, Dq);

    // LN1
    ln_split_kernel<<<Mq, 256>>>(x, g1, be1, p_h_hi, p_h_lo);
    // QKV projection -> split bf16, q prescaled
    gemm_bf16x3<4><<<dim3(3 * Dq / 128, Mq / 128), 256, gemm_smem>>>(
        p_h_hi, p_h_lo, p_wqkv_hi, p_wqkv_lo, nullptr, nullptr,
        nullptr, p_qkvh, p_qkvl, 3 * Dq, Dq);
    // tensor-core flash attention -> split bf16
    flash_tc<<<dim3(Tq / 128, Bq * Hq), 256, FLASH_SMEM>>>(
        p_qkvh, p_qkvl, p_attn_hi, p_attn_lo);
    // output projection + bias + residual(x)
    gemm_bf16x3<2><<<dim3(Dq / 128, Mq / 128), 256, gemm_smem>>>(
        p_attn_hi, p_attn_lo, p_wp_hi, p_wp_lo, bp, x,
        p_x1, nullptr, nullptr, Dq, Dq);
    // LN2
    ln_split_kernel<<<Mq, 256>>>(p_x1, g2, be2, p_h_hi, p_h_lo);
    // FFN up + bias + relu
    gemm_bf16x3<3><<<dim3(DFF / 128, Mq / 128), 256, gemm_smem>>>(
        p_h_hi, p_h_lo, p_w1_hi, p_w1_lo, b1, nullptr,
        nullptr, p_ff_hi, p_ff_lo, DFF, Dq);
    // FFN down + bias + residual(x1) -> d_out
    gemm_bf16x3<2><<<dim3(Dq / 128, Mq / 128), 256, gemm_smem>>>(
        p_ff_hi, p_ff_lo, p_w2_hi, p_w2_lo, b2, p_x1,
        out, nullptr, nullptr, Dq, DFF);
}

// round 5
// speedup vs baseline: 2.8892x; 1.0044x over previous
#include <cuda_runtime.h>
#include <cuda_bf16.h>
#include <stdint.h>

// Problem constants
#define Bq   4
#define Tq   2048
#define Dq   1024
#define Hq   16
#define HDq  64
#define Mq   (Bq * Tq)        // 8192 rows
#define DFF  (4 * Dq)         // 4096
#define LN_EPS 1e-5f
#define ATT_SCALE 0.125f      // HD^-0.5

// ---------------------------------------------------------------------------
// Scratch (static device globals: allocation-free, graph-capture safe)
// ---------------------------------------------------------------------------
__device__ __nv_bfloat16 g_h_hi[Mq * Dq],    g_h_lo[Mq * Dq];
__device__ __nv_bfloat16 g_wqkv_hi[3*Dq*Dq], g_wqkv_lo[3*Dq*Dq];     // [3D][D]
__device__ __nv_bfloat16 g_wp_hi[Dq*Dq],     g_wp_lo[Dq*Dq];         // [D][D] transposed
__device__ __nv_bfloat16 g_w1_hi[Dq*DFF],    g_w1_lo[Dq*DFF];        // [4D][D]
__device__ __nv_bfloat16 g_w2_hi[DFF*Dq],    g_w2_lo[DFF*Dq];        // [D][4D]
__device__ __nv_bfloat16 g_qkvh[Mq * 3 * Dq], g_qkvl[Mq * 3 * Dq];   // q pre-scaled
__device__ __nv_bfloat16 g_attn_hi[Mq * Dq], g_attn_lo[Mq * Dq];
__device__ float         g_x1[Mq * Dq];
__device__ __nv_bfloat16 g_ff_hi[Mq * DFF],  g_ff_lo[Mq * DFF];

// ---------------------------------------------------------------------------
// Helpers
// ---------------------------------------------------------------------------
__device__ __forceinline__ void split_bf16(float v, __nv_bfloat16& hi, __nv_bfloat16& lo) {
    hi = __float2bfloat16(v);
    lo = __float2bfloat16(v - __bfloat162float(hi));
}

__device__ __forceinline__ uint32_t pack2(float x, float y, uint32_t& lo) {
    __nv_bfloat16 hx = __float2bfloat16(x), hy = __float2bfloat16(y);
    __nv_bfloat16 lx = __float2bfloat16(x - __bfloat162float(hx));
    __nv_bfloat16 ly = __float2bfloat16(y - __bfloat162float(hy));
    __nv_bfloat162 h2(hx, hy), l2(lx, ly);
    lo = *reinterpret_cast<uint32_t*>(&l2);
    return *reinterpret_cast<uint32_t*>(&h2);
}

__device__ __forceinline__ void mma16816(float* c, const uint32_t* a, const uint32_t* b) {
    asm volatile(
        "mma.sync.aligned.m16n8k16.row.col.f32.bf16.bf16.f32 "
        "{%0,%1,%2,%3}, {%4,%5,%6,%7}, {%8,%9}, {%0,%1,%2,%3};"
        : "+f"(c[0]), "+f"(c[1]), "+f"(c[2]), "+f"(c[3])
        : "r"(a[0]), "r"(a[1]), "r"(a[2]), "r"(a[3]), "r"(b[0]), "r"(b[1]));
}

__device__ __forceinline__ void ldmx2t(uint32_t& r0, uint32_t& r1, const void* p) {
    uint32_t a = (uint32_t)__cvta_generic_to_shared(p);
    asm volatile("ldmatrix.sync.aligned.m8n8.x2.trans.shared.b16 {%0,%1}, [%2];"
                 : "=r"(r0), "=r"(r1) : "r"(a));
}

__device__ __forceinline__ void cp16(void* sdst, const void* gsrc) {
    unsigned sa = (unsigned)__cvta_generic_to_shared(sdst);
    asm volatile("cp.async.cg.shared.global [%0], [%1], 16;" :: "r"(sa), "l"(gsrc));
}
#define CP_COMMIT() asm volatile("cp.async.commit_group;")
#define CP_WAIT0()  asm volatile("cp.async.wait_group 0;")
#define CP_WAIT1()  asm volatile("cp.async.wait_group 1;")

// ---------------------------------------------------------------------------
// Weight prep: coalesced tiled transpose + split
// ---------------------------------------------------------------------------
__global__ void prep_wqkv_tiled(const float* __restrict__ Wq,
                                const float* __restrict__ Wk,
                                const float* __restrict__ Wv,
                                __nv_bfloat16* __restrict__ o_hi,
                                __nv_bfloat16* __restrict__ o_lo)
{
    __shared__ float t[32][33];
    int s = blockIdx.z >> 4, h = blockIdx.z & 15;
    const float* W = (s == 0) ? Wq : (s == 1) ? Wk : Wv;
    const float* in = W + (long)h * Dq * HDq;    // [D][64]
    int d0 = blockIdx.y * 32, hd0 = blockIdx.x * 32;
    int tx = threadIdx.x, ty = threadIdx.y;
    #pragma unroll
    for (int i = 0; i < 32; i += 8)
        t[ty + i][tx] = in[(long)(d0 + ty + i) * HDq + hd0 + tx];
    __syncthreads();
    long nrow = (long)s * Dq + h * HDq + hd0;
    #pragma unroll
    for (int i = 0; i < 32; i += 8) {
        float v = t[tx][ty + i];
        long o = (nrow + ty + i) * Dq + d0 + tx;
        split_bf16(v, o_hi[o], o_lo[o]);
    }
}

// in: [K][N] fp32 -> out: [N][K] split bf16
__global__ void transpose_split_t(const float* __restrict__ in,
                                  __nv_bfloat16* __restrict__ o_hi,
                                  __nv_bfloat16* __restrict__ o_lo,
                                  int K, int N)
{
    __shared__ float t[32][33];
    int k0 = blockIdx.y * 32, n0 = blockIdx.x * 32;
    int tx = threadIdx.x, ty = threadIdx.y;
    #pragma unroll
    for (int i = 0; i < 32; i += 8)
        t[ty + i][tx] = in[(long)(k0 + ty + i) * N + n0 + tx];
    __syncthreads();
    #pragma unroll
    for (int i = 0; i < 32; i += 8) {
        float v = t[tx][ty + i];
        long o = (long)(n0 + ty + i) * K + k0 + tx;
        split_bf16(v, o_hi[o], o_lo[o]);
    }
}

// ---------------------------------------------------------------------------
// LayerNorm -> split bf16
// ---------------------------------------------------------------------------
__global__ void ln_split_kernel(const float* __restrict__ x,
                                const float* __restrict__ g,
                                const float* __restrict__ b,
                                __nv_bfloat16* __restrict__ o_hi,
                                __nv_bfloat16* __restrict__ o_lo)
{
    __shared__ float red[16];
    int row = blockIdx.x;
    int t = threadIdx.x;
    const float4* xr = (const float4*)(x + (long)row * Dq);
    float4 v = xr[t];
    float s  = v.x + v.y + v.z + v.w;
    float ss = v.x * v.x + v.y * v.y + v.z * v.z + v.w * v.w;
    #pragma unroll
    for (int o = 16; o >= 1; o >>= 1) {
        s  += __shfl_xor_sync(0xffffffffu, s,  o);
        ss += __shfl_xor_sync(0xffffffffu, ss, o);
    }
    if ((t & 31) == 0) { red[t >> 5] = s; red[8 + (t >> 5)] = ss; }
    __syncthreads();
    float stot = 0.f, sstot = 0.f;
    #pragma unroll
    for (int w = 0; w < 8; w++) { stot += red[w]; sstot += red[8 + w]; }
    float mu  = stot * (1.f / Dq);
    float var = sstot * (1.f / Dq) - mu * mu;
    float inv = rsqrtf(var + LN_EPS);
    float4 gg = ((const float4*)g)[t];
    float4 bb = ((const float4*)b)[t];
    float o0 = (v.x - mu) * inv * gg.x + bb.x;
    float o1 = (v.y - mu) * inv * gg.y + bb.y;
    float o2 = (v.z - mu) * inv * gg.z + bb.z;
    float o3 = (v.w - mu) * inv * gg.w + bb.w;
    __nv_bfloat16 h0,l0,h1,l1,h2,l2,h3,l3;
    split_bf16(o0,h0,l0); split_bf16(o1,h1,l1);
    split_bf16(o2,h2,l2); split_bf16(o3,h3,l3);
    long base = (long)row * Dq + t * 4;
    *(__nv_bfloat162*)(o_hi + base)     = __nv_bfloat162(h0, h1);
    *(__nv_bfloat162*)(o_hi + base + 2) = __nv_bfloat162(h2, h3);
    *(__nv_bfloat162*)(o_lo + base)     = __nv_bfloat162(l0, l1);
    *(__nv_bfloat162*)(o_lo + base + 2) = __nv_bfloat162(l2, l3);
}

// ---------------------------------------------------------------------------
// bf16x3 tensor-core GEMM: C[M,N] = A[M,K] @ B[K,N], B pre-transposed [N][K].
// Tile 128x256, BK=32, 256 threads (8 warps 2x4), warp tile 64x64,
// 3-stage cp.async pipeline (prefetch distance 2, wait_group 1).
// EPI: 0 fp32; 2 +bias+residual fp32; 3 +bias+relu -> split bf16;
//      4 split bf16 w/ q prescale (QKV)
// ---------------------------------------------------------------------------
#define KPAD 40
#define AP_E (128 * KPAD)
#define BP_E (256 * KPAD)
#define STAGE_E (2 * AP_E + 2 * BP_E)          // 30720 elems = 61440 B
#define GEMM_SMEM (3 * STAGE_E * 2)            // 184320 B

template <int EPI>
__global__ void __launch_bounds__(256, 1)
gemm_bf16x3(const __nv_bfloat16* __restrict__ Ahi,
            const __nv_bfloat16* __restrict__ Alo,
            const __nv_bfloat16* __restrict__ Bhi,
            const __nv_bfloat16* __restrict__ Blo,
            const float* __restrict__ bias,
            const float* __restrict__ res,
            float* __restrict__ C,
            __nv_bfloat16* __restrict__ Chi,
            __nv_bfloat16* __restrict__ Clo,
            int N, int K)
{
    extern __shared__ __nv_bfloat16 smem[];
    const int tid  = threadIdx.x;
    const int lane = tid & 31;
    const int warp = tid >> 5;
    const int wm = warp >> 2;          // 0..1  (64 rows each)
    const int wn = warp & 3;           // 0..3  (64 cols each)
    const int fr = lane >> 2;          // 0..7
    const int fc = (lane & 3) * 2;

    const int bm = blockIdx.y, bn = blockIdx.x;
    const __nv_bfloat16* Ahi_b = Ahi + (long)bm * 128 * K;
    const __nv_bfloat16* Alo_b = Alo + (long)bm * 128 * K;
    const __nv_bfloat16* Bhi_b = Bhi + (long)bn * 256 * K;
    const __nv_bfloat16* Blo_b = Blo + (long)bn * 256 * K;

    auto sA = [&](int st, int p) -> __nv_bfloat16* {
        return smem + st * STAGE_E + p * AP_E;
    };
    auto sB = [&](int st, int p) -> __nv_bfloat16* {
        return smem + st * STAGE_E + 2 * AP_E + p * BP_E;
    };

    auto ld_tile = [&](int st, int kt) {
        long k0 = (long)kt * 32;
        #pragma unroll
        for (int i = 0; i < 2; i++) {               // A: 128 rows x 4 chunks
            int c = tid + i * 256;
            int row = c >> 2, ch = (c & 3) * 8;
            long go = (long)row * K + k0 + ch;
            int  so = row * KPAD + ch;
            cp16(sA(st,0) + so, Ahi_b + go);
            cp16(sA(st,1) + so, Alo_b + go);
        }
        #pragma unroll
        for (int i = 0; i < 4; i++) {               // B: 256 rows x 4 chunks
            int c = tid + i * 256;
            int row = c >> 2, ch = (c & 3) * 8;
            long go = (long)row * K + k0 + ch;
            int  so = row * KPAD + ch;
            cp16(sB(st,0) + so, Bhi_b + go);
            cp16(sB(st,1) + so, Blo_b + go);
        }
    };

    float acc[4][8][4];
    #pragma unroll
    for (int i = 0; i < 4; i++)
        #pragma unroll
        for (int j = 0; j < 8; j++)
            #pragma unroll
            for (int r = 0; r < 4; r++) acc[i][j][r] = 0.f;

    const int KT = K / 32;
    ld_tile(0, 0); CP_COMMIT();
    ld_tile(1, 1); CP_COMMIT();

    int st = 0;
    for (int kt = 0; kt < KT; kt++) {
        if (kt + 1 < KT) { CP_WAIT1(); } else { CP_WAIT0(); }
        __syncthreads();
        if (kt + 2 < KT) {
            int wst = st + 2; if (wst >= 3) wst -= 3;
            ld_tile(wst, kt + 2);
            CP_COMMIT();
        }

        const __nv_bfloat16* sAh = sA(st, 0);
        const __nv_bfloat16* sAl = sA(st, 1);
        const __nv_bfloat16* sBh = sB(st, 0);
        const __nv_bfloat16* sBl = sB(st, 1);

        #pragma unroll
        for (int ks = 0; ks < 2; ks++) {
            uint32_t ah[4][4], al[4][4], bh[8][2], bl[8][2];
            #pragma unroll
            for (int mt = 0; mt < 4; mt++) {
                int row = wm * 64 + mt * 16 + fr;
                int col = ks * 16 + fc;
                const __nv_bfloat16* pa = sAh + row * KPAD + col;
                const __nv_bfloat16* pl = sAl + row * KPAD + col;
                ah[mt][0] = *(const uint32_t*)pa;
                ah[mt][1] = *(const uint32_t*)(pa + 8 * KPAD);
                ah[mt][2] = *(const uint32_t*)(pa + 8);
                ah[mt][3] = *(const uint32_t*)(pa + 8 * KPAD + 8);
                al[mt][0] = *(const uint32_t*)pl;
                al[mt][1] = *(const uint32_t*)(pl + 8 * KPAD);
                al[mt][2] = *(const uint32_t*)(pl + 8);
                al[mt][3] = *(const uint32_t*)(pl + 8 * KPAD + 8);
            }
            #pragma unroll
            for (int nt = 0; nt < 8; nt++) {
                int n = wn * 64 + nt * 8 + fr;
                int k = ks * 16 + fc;
                const __nv_bfloat16* pb = sBh + n * KPAD + k;
                const __nv_bfloat16* pq = sBl + n * KPAD + k;
                bh[nt][0] = *(const uint32_t*)pb;
                bh[nt][1] = *(const uint32_t*)(pb + 8);
                bl[nt][0] = *(const uint32_t*)pq;
                bl[nt][1] = *(const uint32_t*)(pq + 8);
            }
            #pragma unroll
            for (int mt = 0; mt < 4; mt++)
                #pragma unroll
                for (int nt = 0; nt < 8; nt++) {
                    mma16816(acc[mt][nt], ah[mt], bh[nt]);
                    mma16816(acc[mt][nt], ah[mt], bl[nt]);
                    mma16816(acc[mt][nt], al[mt], bh[nt]);
                }
        }
        __syncthreads();
        if (++st == 3) st = 0;
    }

    // epilogue
    const int lr4 = lane >> 2;
    const int lc2 = (lane & 3) * 2;
    #pragma unroll
    for (int mt = 0; mt < 4; mt++) {
        #pragma unroll
        for (int nt = 0; nt < 8; nt++) {
            int c = bn * 256 + wn * 64 + nt * 8 + lc2;
            #pragma unroll
            for (int half = 0; half < 2; half++) {
                int r = bm * 128 + wm * 64 + mt * 16 + lr4 + half * 8;
                float v0 = acc[mt][nt][half * 2 + 0];
                float v1 = acc[mt][nt][half * 2 + 1];
                long off = (long)r * N + c;
                if (EPI == 0) {
                    *(float2*)(C + off) = make_float2(v0, v1);
                } else if (EPI == 2) {
                    float2 bv = *(const float2*)(bias + c);
                    float2 rv = *(const float2*)(res + off);
                    *(float2*)(C + off) = make_float2(v0 + bv.x + rv.x,
                                                      v1 + bv.y + rv.y);
                } else if (EPI == 3) {
                    float2 bv = *(const float2*)(bias + c);
                    v0 = fmaxf(v0 + bv.x, 0.f);
                    v1 = fmaxf(v1 + bv.y, 0.f);
                    uint32_t lo;
                    uint32_t hi = pack2(v0, v1, lo);
                    *(uint32_t*)(Chi + off) = hi;
                    *(uint32_t*)(Clo + off) = lo;
                } else {  // EPI == 4: QKV split out, q cols prescaled
                    float scale = (c < Dq) ? ATT_SCALE : 1.f;
                    uint32_t lo;
                    uint32_t hi = pack2(v0 * scale, v1 * scale, lo);
                    *(uint32_t*)(Chi + off) = hi;
                    *(uint32_t*)(Clo + off) = lo;
                }
            }
        }
    }
}

// ---------------------------------------------------------------------------
// Tensor-core flash attention (bf16x3, FA2 register pipeline) — proven in R3
// ---------------------------------------------------------------------------
#define FPAD 72
#define FLASH_SMEM ((2 * 128 * FPAD + 2 * 4 * 64 * FPAD) * 2)

__global__ void __launch_bounds__(256)
flash_tc(const __nv_bfloat16* __restrict__ qkvh,
         const __nv_bfloat16* __restrict__ qkvl,
         __nv_bfloat16* __restrict__ out_hi,
         __nv_bfloat16* __restrict__ out_lo)
{
    extern __shared__ __nv_bfloat16 sm[];
    __nv_bfloat16* QH = sm;
    __nv_bfloat16* QL = sm + 128 * FPAD;

    const int qi  = gridDim.x - 1 - blockIdx.x;
    const int bh  = blockIdx.y;
    const int b   = bh >> 4;
    const int h   = bh & 15;
    const int tid  = threadIdx.x;
    const int lane = tid & 31;
    const int warp = tid >> 5;
    const int g  = lane >> 2;
    const int t2 = (lane & 3) * 2;

    const long rb = (long)b * Tq;
    const __nv_bfloat16* qh = qkvh + (rb + qi * 128) * (3 * Dq) + h * HDq;
    const __nv_bfloat16* ql = qkvl + (rb + qi * 128) * (3 * Dq) + h * HDq;
    const __nv_bfloat16* kh = qkvh + rb * (3 * Dq) + Dq + h * HDq;
    const __nv_bfloat16* kl = qkvl + rb * (3 * Dq) + Dq + h * HDq;
    const __nv_bfloat16* vh = qkvh + rb * (3 * Dq) + 2 * Dq + h * HDq;
    const __nv_bfloat16* vl = qkvl + rb * (3 * Dq) + 2 * Dq + h * HDq;

    auto kvbase = [&](int st) -> __nv_bfloat16* {
        return sm + 2 * 128 * FPAD + st * (4 * 64 * FPAD);
    };
    auto ldkv = [&](int st, int jt) {
        __nv_bfloat16* KB = kvbase(st);
        #pragma unroll
        for (int i = 0; i < 2; i++) {
            int c = tid + i * 256;
            int row = c >> 3;
            int c8 = (c & 7) * 8;
            long go = (long)(jt * 64 + row) * (3 * Dq) + c8;
            int so = row * FPAD + c8;
            cp16(KB + so,                 kh + go);
            cp16(KB + 64 * FPAD + so,     kl + go);
            cp16(KB + 2 * 64 * FPAD + so, vh + go);
            cp16(KB + 3 * 64 * FPAD + so, vl + go);
        }
    };

    #pragma unroll
    for (int i = 0; i < 4; i++) {
        int c = tid + i * 256;
        int row = c >> 3;
        int c8 = (c & 7) * 8;
        cp16(QH + row * FPAD + c8, qh + (long)row * (3 * Dq) + c8);
        cp16(QL + row * FPAD + c8, ql + (long)row * (3 * Dq) + c8);
    }
    ldkv(0, 0);
    CP_COMMIT();

    float oacc[8][4];
    #pragma unroll
    for (int nt = 0; nt < 8; nt++)
        #pragma unroll
        for (int e = 0; e < 4; e++) oacc[nt][e] = 0.f;
    float m0 = -1e30f, m1 = -1e30f, l0 = 0.f, l1 = 0.f;

    const int qrow0 = qi * 128 + warp * 16 + g;
    const int jmax = 2 * qi + 1;

    for (int jt = 0; jt <= jmax; jt++) {
        CP_WAIT0();
        __syncthreads();
        if (jt < jmax) { ldkv((jt + 1) & 1, jt + 1); CP_COMMIT(); }

        if (jt * 64 <= qi * 128 + warp * 16 + 15) {
            __nv_bfloat16* KB = kvbase(jt & 1);
            const __nv_bfloat16* KHs = KB;
            const __nv_bfloat16* KLs = KB + 64 * FPAD;
            const __nv_bfloat16* VHs = KB + 2 * 64 * FPAD;
            const __nv_bfloat16* VLs = KB + 3 * 64 * FPAD;

            float sacc[8][4];
            #pragma unroll
            for (int nt = 0; nt < 8; nt++)
                #pragma unroll
                for (int e = 0; e < 4; e++) sacc[nt][e] = 0.f;

            #pragma unroll
            for (int kt = 0; kt < 4; kt++) {
                uint32_t ah[4], al[4];
                const __nv_bfloat16* pa = QH + (warp * 16 + g) * FPAD + kt * 16 + t2;
                const __nv_bfloat16* pl = QL + (warp * 16 + g) * FPAD + kt * 16 + t2;
                ah[0] = *(const uint32_t*)pa;
                ah[1] = *(const uint32_t*)(pa + 8 * FPAD);
                ah[2] = *(const uint32_t*)(pa + 8);
                ah[3] = *(const uint32_t*)(pa + 8 * FPAD + 8);
                al[0] = *(const uint32_t*)pl;
                al[1] = *(const uint32_t*)(pl + 8 * FPAD);
                al[2] = *(const uint32_t*)(pl + 8);
                al[3] = *(const uint32_t*)(pl + 8 * FPAD + 8);
                #pragma unroll
                for (int nt = 0; nt < 8; nt++) {
                    const __nv_bfloat16* pb = KHs + (nt * 8 + g) * FPAD + kt * 16 + t2;
                    const __nv_bfloat16* pq = KLs + (nt * 8 + g) * FPAD + kt * 16 + t2;
                    uint32_t bhf[2] = { *(const uint32_t*)pb, *(const uint32_t*)(pb + 8) };
                    uint32_t blf[2] = { *(const uint32_t*)pq, *(const uint32_t*)(pq + 8) };
                    mma16816(sacc[nt], ah, bhf);
                    mma16816(sacc[nt], ah, blf);
                    mma16816(sacc[nt], al, bhf);
                }
            }

            if (jt * 64 + 63 > qrow0) {
                #pragma unroll
                for (int nt = 0; nt < 8; nt++) {
                    int key0 = jt * 64 + nt * 8 + t2;
                    if (key0     > qrow0)     sacc[nt][0] = -1e30f;
                    if (key0 + 1 > qrow0)     sacc[nt][1] = -1e30f;
                    if (key0     > qrow0 + 8) sacc[nt][2] = -1e30f;
                    if (key0 + 1 > qrow0 + 8) sacc[nt][3] = -1e30f;
                }
            }

            float mx0 = -1e30f, mx1 = -1e30f;
            #pragma unroll
            for (int nt = 0; nt < 8; nt++) {
                mx0 = fmaxf(mx0, fmaxf(sacc[nt][0], sacc[nt][1]));
                mx1 = fmaxf(mx1, fmaxf(sacc[nt][2], sacc[nt][3]));
            }
            mx0 = fmaxf(mx0, __shfl_xor_sync(0xffffffffu, mx0, 1));
            mx0 = fmaxf(mx0, __shfl_xor_sync(0xffffffffu, mx0, 2));
            mx1 = fmaxf(mx1, __shfl_xor_sync(0xffffffffu, mx1, 1));
            mx1 = fmaxf(mx1, __shfl_xor_sync(0xffffffffu, mx1, 2));
            float mn0 = fmaxf(m0, mx0), mn1 = fmaxf(m1, mx1);
            float a0 = __expf(m0 - mn0), a1 = __expf(m1 - mn1);
            m0 = mn0; m1 = mn1;
            float rs0 = 0.f, rs1 = 0.f;
            #pragma unroll
            for (int nt = 0; nt < 8; nt++) {
                sacc[nt][0] = __expf(sacc[nt][0] - mn0); rs0 += sacc[nt][0];
                sacc[nt][1] = __expf(sacc[nt][1] - mn0); rs0 += sacc[nt][1];
                sacc[nt][2] = __expf(sacc[nt][2] - mn1); rs1 += sacc[nt][2];
                sacc[nt][3] = __expf(sacc[nt][3] - mn1); rs1 += sacc[nt][3];
            }
            rs0 += __shfl_xor_sync(0xffffffffu, rs0, 1);
            rs0 += __shfl_xor_sync(0xffffffffu, rs0, 2);
            rs1 += __shfl_xor_sync(0xffffffffu, rs1, 1);
            rs1 += __shfl_xor_sync(0xffffffffu, rs1, 2);
            l0 = l0 * a0 + rs0;
            l1 = l1 * a1 + rs1;
            #pragma unroll
            for (int nt = 0; nt < 8; nt++) {
                oacc[nt][0] *= a0; oacc[nt][1] *= a0;
                oacc[nt][2] *= a1; oacc[nt][3] *= a1;
            }

            #pragma unroll
            for (int j = 0; j < 4; j++) {
                uint32_t ph[4], pl4[4];
                ph[0] = pack2(sacc[2*j][0],   sacc[2*j][1],   pl4[0]);
                ph[1] = pack2(sacc[2*j][2],   sacc[2*j][3],   pl4[1]);
                ph[2] = pack2(sacc[2*j+1][0], sacc[2*j+1][1], pl4[2]);
                ph[3] = pack2(sacc[2*j+1][2], sacc[2*j+1][3], pl4[3]);
                #pragma unroll
                for (int nt = 0; nt < 8; nt++) {
                    uint32_t vhf[2], vlf[2];
                    ldmx2t(vhf[0], vhf[1], VHs + (j * 16 + (lane & 15)) * FPAD + nt * 8);
                    ldmx2t(vlf[0], vlf[1], VLs + (j * 16 + (lane & 15)) * FPAD + nt * 8);
                    mma16816(oacc[nt], ph, vhf);
                    mma16816(oacc[nt], ph, vlf);
                    mma16816(oacc[nt], pl4, vhf);
                }
            }
        }
        __syncthreads();
    }

    float inv0 = 1.f / l0, inv1 = 1.f / l1;
    long row0 = (long)b * Tq + qi * 128 + warp * 16 + g;
    #pragma unroll
    for (int nt = 0; nt < 8; nt++) {
        int col = h * HDq + nt * 8 + t2;
        uint32_t lo;
        uint32_t hi = pack2(oacc[nt][0] * inv0, oacc[nt][1] * inv0, lo);
        *(uint32_t*)(out_hi + row0 * Dq + col) = hi;
        *(uint32_t*)(out_lo + row0 * Dq + col) = lo;
        hi = pack2(oacc[nt][2] * inv1, oacc[nt][3] * inv1, lo);
        *(uint32_t*)(out_hi + (row0 + 8) * Dq + col) = hi;
        *(uint32_t*)(out_lo + (row0 + 8) * Dq + col) = lo;
    }
}

// ---------------------------------------------------------------------------
// Launch
// ---------------------------------------------------------------------------
extern "C" void kernel_launch(void* const* d_in, const int* in_sizes, int n_in,
                              void* d_out, int out_size)
{
    const float* x   = (const float*)d_in[0];
    const float* Wq  = (const float*)d_in[1];
    const float* Wk  = (const float*)d_in[2];
    const float* Wv  = (const float*)d_in[3];
    const float* Wp  = (const float*)d_in[4];
    const float* bp  = (const float*)d_in[5];
    const float* W1  = (const float*)d_in[6];
    const float* b1  = (const float*)d_in[7];
    const float* W2  = (const float*)d_in[8];
    const float* b2  = (const float*)d_in[9];
    const float* g1  = (const float*)d_in[10];
    const float* be1 = (const float*)d_in[11];
    const float* g2  = (const float*)d_in[12];
    const float* be2 = (const float*)d_in[13];
    float* out = (float*)d_out;

    __nv_bfloat16 *p_h_hi, *p_h_lo, *p_wqkv_hi, *p_wqkv_lo, *p_wp_hi, *p_wp_lo;
    __nv_bfloat16 *p_w1_hi, *p_w1_lo, *p_w2_hi, *p_w2_lo;
    __nv_bfloat16 *p_attn_hi, *p_attn_lo, *p_ff_hi, *p_ff_lo, *p_qkvh, *p_qkvl;
    float *p_x1;
    cudaGetSymbolAddress((void**)&p_h_hi,    g_h_hi);
    cudaGetSymbolAddress((void**)&p_h_lo,    g_h_lo);
    cudaGetSymbolAddress((void**)&p_wqkv_hi, g_wqkv_hi);
    cudaGetSymbolAddress((void**)&p_wqkv_lo, g_wqkv_lo);
    cudaGetSymbolAddress((void**)&p_wp_hi,   g_wp_hi);
    cudaGetSymbolAddress((void**)&p_wp_lo,   g_wp_lo);
    cudaGetSymbolAddress((void**)&p_w1_hi,   g_w1_hi);
    cudaGetSymbolAddress((void**)&p_w1_lo,   g_w1_lo);
    cudaGetSymbolAddress((void**)&p_w2_hi,   g_w2_hi);
    cudaGetSymbolAddress((void**)&p_w2_lo,   g_w2_lo);
    cudaGetSymbolAddress((void**)&p_qkvh,    g_qkvh);
    cudaGetSymbolAddress((void**)&p_qkvl,    g_qkvl);
    cudaGetSymbolAddress((void**)&p_attn_hi, g_attn_hi);
    cudaGetSymbolAddress((void**)&p_attn_lo, g_attn_lo);
    cudaGetSymbolAddress((void**)&p_x1,      g_x1);
    cudaGetSymbolAddress((void**)&p_ff_hi,   g_ff_hi);
    cudaGetSymbolAddress((void**)&p_ff_lo,   g_ff_lo);

    cudaFuncSetAttribute(gemm_bf16x3<2>, cudaFuncAttributeMaxDynamicSharedMemorySize, GEMM_SMEM);
    cudaFuncSetAttribute(gemm_bf16x3<3>, cudaFuncAttributeMaxDynamicSharedMemorySize, GEMM_SMEM);
    cudaFuncSetAttribute(gemm_bf16x3<4>, cudaFuncAttributeMaxDynamicSharedMemorySize, GEMM_SMEM);
    cudaFuncSetAttribute(flash_tc,       cudaFuncAttributeMaxDynamicSharedMemorySize, FLASH_SMEM);

    // weight prep (coalesced tiled transposes)
    prep_wqkv_tiled<<<dim3(HDq / 32, Dq / 32, 48), dim3(32, 8)>>>(Wq, Wk, Wv, p_wqkv_hi, p_wqkv_lo);
    transpose_split_t<<<dim3(Dq / 32, Dq / 32),  dim3(32, 8)>>>(Wp, p_wp_hi, p_wp_lo, Dq, Dq);
    transpose_split_t<<<dim3(DFF / 32, Dq / 32), dim3(32, 8)>>>(W1, p_w1_hi, p_w1_lo, Dq, DFF);
    transpose_split_t<<<dim3(Dq / 32, DFF / 32), dim3(32, 8)>>>(W2, p_w2_hi, p_w2_lo, DFF, Dq);

    // LN1
    ln_split_kernel<<<Mq, 256>>>(x, g1, be1, p_h_hi, p_h_lo);
    // QKV projection -> split bf16, q prescaled
    gemm_bf16x3<4><<<dim3(3 * Dq / 256, Mq / 128), 256, GEMM_SMEM>>>(
        p_h_hi, p_h_lo, p_wqkv_hi, p_wqkv_lo, nullptr, nullptr,
        nullptr, p_qkvh, p_qkvl, 3 * Dq, Dq);
    // flash attention
    flash_tc<<<dim3(Tq / 128, Bq * Hq), 256, FLASH_SMEM>>>(
        p_qkvh, p_qkvl, p_attn_hi, p_attn_lo);
    // output projection + bias + residual(x)
    gemm_bf16x3<2><<<dim3(Dq / 256, Mq / 128), 256, GEMM_SMEM>>>(
        p_attn_hi, p_attn_lo, p_wp_hi, p_wp_lo, bp, x,
        p_x1, nullptr, nullptr, Dq, Dq);
    // LN2
    ln_split_kernel<<<Mq, 256>>>(p_x1, g2, be2, p_h_hi, p_h_lo);
    // FFN up + bias + relu
    gemm_bf16x3<3><<<dim3(DFF / 256, Mq / 128), 256, GEMM_SMEM>>>(
        p_h_hi, p_h_lo, p_w1_hi, p_w1_lo, b1, nullptr,
        nullptr, p_ff_hi, p_ff_lo, DFF, Dq);
    // FFN down + bias + residual(x1) -> d_out
    gemm_bf16x3<2><<<dim3(Dq / 256, Mq / 128), 256, GEMM_SMEM>>>(
        p_ff_hi, p_ff_lo, p_w2_hi, p_w2_lo, b2, p_x1,
        out, nullptr, nullptr, Dq, DFF);
}

// round 6
// speedup vs baseline: 2.9252x; 1.0125x over previous
#include <cuda_runtime.h>
#include <cuda_bf16.h>
#include <stdint.h>

// Problem constants
#define Bq   4
#define Tq   2048
#define Dq   1024
#define Hq   16
#define HDq  64
#define Mq   (Bq * Tq)        // 8192 rows
#define DFF  (4 * Dq)         // 4096
#define LN_EPS 1e-5f
#define ATT_SCALE 0.125f      // HD^-0.5

// ---------------------------------------------------------------------------
// Scratch (static device globals)
// ---------------------------------------------------------------------------
__device__ __nv_bfloat16 g_h_hi[Mq * Dq],    g_h_lo[Mq * Dq];
__device__ __nv_bfloat16 g_wqkv_hi[3*Dq*Dq], g_wqkv_lo[3*Dq*Dq];     // [3D][D]
__device__ __nv_bfloat16 g_wp_hi[Dq*Dq],     g_wp_lo[Dq*Dq];         // [D][D] transposed
__device__ __nv_bfloat16 g_w1_hi[Dq*DFF],    g_w1_lo[Dq*DFF];        // [4D][D]
__device__ __nv_bfloat16 g_w2_hi[DFF*Dq],    g_w2_lo[DFF*Dq];        // [D][4D]
__device__ __nv_bfloat16 g_qkvh[Mq * 3 * Dq], g_qkvl[Mq * 3 * Dq];   // q pre-scaled
__device__ __nv_bfloat16 g_attn_hi[Mq * Dq], g_attn_lo[Mq * Dq];
__device__ float         g_x1[Mq * Dq];
__device__ __nv_bfloat16 g_ff_hi[Mq * DFF],  g_ff_lo[Mq * DFF];

// ---------------------------------------------------------------------------
// Helpers
// ---------------------------------------------------------------------------
__device__ __forceinline__ void split_bf16(float v, __nv_bfloat16& hi, __nv_bfloat16& lo) {
    hi = __float2bfloat16(v);
    lo = __float2bfloat16(v - __bfloat162float(hi));
}

__device__ __forceinline__ uint32_t pack2(float x, float y, uint32_t& lo) {
    __nv_bfloat16 hx = __float2bfloat16(x), hy = __float2bfloat16(y);
    __nv_bfloat16 lx = __float2bfloat16(x - __bfloat162float(hx));
    __nv_bfloat16 ly = __float2bfloat16(y - __bfloat162float(hy));
    __nv_bfloat162 h2(hx, hy), l2(lx, ly);
    lo = *reinterpret_cast<uint32_t*>(&l2);
    return *reinterpret_cast<uint32_t*>(&h2);
}

__device__ __forceinline__ void mma16816(float* c, const uint32_t* a, const uint32_t* b) {
    asm volatile(
        "mma.sync.aligned.m16n8k16.row.col.f32.bf16.bf16.f32 "
        "{%0,%1,%2,%3}, {%4,%5,%6,%7}, {%8,%9}, {%0,%1,%2,%3};"
        : "+f"(c[0]), "+f"(c[1]), "+f"(c[2]), "+f"(c[3])
        : "r"(a[0]), "r"(a[1]), "r"(a[2]), "r"(a[3]), "r"(b[0]), "r"(b[1]));
}

__device__ __forceinline__ void ldmx4(uint32_t* r, const void* p) {
    uint32_t a = (uint32_t)__cvta_generic_to_shared(p);
    asm volatile("ldmatrix.sync.aligned.m8n8.x4.shared.b16 {%0,%1,%2,%3}, [%4];"
                 : "=r"(r[0]), "=r"(r[1]), "=r"(r[2]), "=r"(r[3]) : "r"(a));
}

__device__ __forceinline__ void ldmx2t(uint32_t& r0, uint32_t& r1, const void* p) {
    uint32_t a = (uint32_t)__cvta_generic_to_shared(p);
    asm volatile("ldmatrix.sync.aligned.m8n8.x2.trans.shared.b16 {%0,%1}, [%2];"
                 : "=r"(r0), "=r"(r1) : "r"(a));
}

__device__ __forceinline__ void cp16(void* sdst, const void* gsrc) {
    unsigned sa = (unsigned)__cvta_generic_to_shared(sdst);
    asm volatile("cp.async.cg.shared.global [%0], [%1], 16;" :: "r"(sa), "l"(gsrc));
}
#define CP_COMMIT() asm volatile("cp.async.commit_group;")
#define CP_WAIT0()  asm volatile("cp.async.wait_group 0;")
#define CP_WAIT1()  asm volatile("cp.async.wait_group 1;")

// ---------------------------------------------------------------------------
// Weight prep: coalesced tiled transpose + split
// ---------------------------------------------------------------------------
__global__ void prep_wqkv_tiled(const float* __restrict__ Wq,
                                const float* __restrict__ Wk,
                                const float* __restrict__ Wv,
                                __nv_bfloat16* __restrict__ o_hi,
                                __nv_bfloat16* __restrict__ o_lo)
{
    __shared__ float t[32][33];
    int s = blockIdx.z >> 4, h = blockIdx.z & 15;
    const float* W = (s == 0) ? Wq : (s == 1) ? Wk : Wv;
    const float* in = W + (long)h * Dq * HDq;    // [D][64]
    int d0 = blockIdx.y * 32, hd0 = blockIdx.x * 32;
    int tx = threadIdx.x, ty = threadIdx.y;
    #pragma unroll
    for (int i = 0; i < 32; i += 8)
        t[ty + i][tx] = in[(long)(d0 + ty + i) * HDq + hd0 + tx];
    __syncthreads();
    long nrow = (long)s * Dq + h * HDq + hd0;
    #pragma unroll
    for (int i = 0; i < 32; i += 8) {
        float v = t[tx][ty + i];
        long o = (nrow + ty + i) * Dq + d0 + tx;
        split_bf16(v, o_hi[o], o_lo[o]);
    }
}

// in: [K][N] fp32 -> out: [N][K] split bf16
__global__ void transpose_split_t(const float* __restrict__ in,
                                  __nv_bfloat16* __restrict__ o_hi,
                                  __nv_bfloat16* __restrict__ o_lo,
                                  int K, int N)
{
    __shared__ float t[32][33];
    int k0 = blockIdx.y * 32, n0 = blockIdx.x * 32;
    int tx = threadIdx.x, ty = threadIdx.y;
    #pragma unroll
    for (int i = 0; i < 32; i += 8)
        t[ty + i][tx] = in[(long)(k0 + ty + i) * N + n0 + tx];
    __syncthreads();
    #pragma unroll
    for (int i = 0; i < 32; i += 8) {
        float v = t[tx][ty + i];
        long o = (long)(n0 + ty + i) * K + k0 + tx;
        split_bf16(v, o_hi[o], o_lo[o]);
    }
}

// ---------------------------------------------------------------------------
// LayerNorm -> split bf16
// ---------------------------------------------------------------------------
__global__ void ln_split_kernel(const float* __restrict__ x,
                                const float* __restrict__ g,
                                const float* __restrict__ b,
                                __nv_bfloat16* __restrict__ o_hi,
                                __nv_bfloat16* __restrict__ o_lo)
{
    __shared__ float red[16];
    int row = blockIdx.x;
    int t = threadIdx.x;
    const float4* xr = (const float4*)(x + (long)row * Dq);
    float4 v = xr[t];
    float s  = v.x + v.y + v.z + v.w;
    float ss = v.x * v.x + v.y * v.y + v.z * v.z + v.w * v.w;
    #pragma unroll
    for (int o = 16; o >= 1; o >>= 1) {
        s  += __shfl_xor_sync(0xffffffffu, s,  o);
        ss += __shfl_xor_sync(0xffffffffu, ss, o);
    }
    if ((t & 31) == 0) { red[t >> 5] = s; red[8 + (t >> 5)] = ss; }
    __syncthreads();
    float stot = 0.f, sstot = 0.f;
    #pragma unroll
    for (int w = 0; w < 8; w++) { stot += red[w]; sstot += red[8 + w]; }
    float mu  = stot * (1.f / Dq);
    float var = sstot * (1.f / Dq) - mu * mu;
    float inv = rsqrtf(var + LN_EPS);
    float4 gg = ((const float4*)g)[t];
    float4 bb = ((const float4*)b)[t];
    float o0 = (v.x - mu) * inv * gg.x + bb.x;
    float o1 = (v.y - mu) * inv * gg.y + bb.y;
    float o2 = (v.z - mu) * inv * gg.z + bb.z;
    float o3 = (v.w - mu) * inv * gg.w + bb.w;
    __nv_bfloat16 h0,l0,h1,l1,h2,l2,h3,l3;
    split_bf16(o0,h0,l0); split_bf16(o1,h1,l1);
    split_bf16(o2,h2,l2); split_bf16(o3,h3,l3);
    long base = (long)row * Dq + t * 4;
    *(__nv_bfloat162*)(o_hi + base)     = __nv_bfloat162(h0, h1);
    *(__nv_bfloat162*)(o_hi + base + 2) = __nv_bfloat162(h2, h3);
    *(__nv_bfloat162*)(o_lo + base)     = __nv_bfloat162(l0, l1);
    *(__nv_bfloat162*)(o_lo + base + 2) = __nv_bfloat162(l2, l3);
}

// ---------------------------------------------------------------------------
// bf16x3 tensor-core GEMM: tile 128x256, BK=32, 8 warps (2x4), warp 64x64.
// ldmatrix.x4 fragment loads, 3-stage cp.async, ONE barrier per K-step.
// EPI: 2 +bias+residual fp32; 3 +bias+relu -> split bf16; 4 split bf16 w/ q prescale
// ---------------------------------------------------------------------------
#define KPAD 40
#define AP_E (128 * KPAD)
#define BP_E (256 * KPAD)
#define STAGE_E (2 * AP_E + 2 * BP_E)          // 30720 elems
#define GEMM_SMEM (3 * STAGE_E * 2)            // 184320 B

template <int EPI>
__global__ void __launch_bounds__(256, 1)
gemm_bf16x3(const __nv_bfloat16* __restrict__ Ahi,
            const __nv_bfloat16* __restrict__ Alo,
            const __nv_bfloat16* __restrict__ Bhi,
            const __nv_bfloat16* __restrict__ Blo,
            const float* __restrict__ bias,
            const float* __restrict__ res,
            float* __restrict__ C,
            __nv_bfloat16* __restrict__ Chi,
            __nv_bfloat16* __restrict__ Clo,
            int N, int K)
{
    extern __shared__ __nv_bfloat16 smem[];
    const int tid  = threadIdx.x;
    const int lane = tid & 31;
    const int warp = tid >> 5;
    const int wm = warp >> 2;          // 0..1
    const int wn = warp & 3;           // 0..3

    // ldmatrix per-lane offsets
    const int a_r = lane & 15;                      // row within m16 tile
    const int a_c = (lane >> 4) << 3;               // 0 or 8 (k offset)
    const int b_r = (lane & 7) + ((lane >> 4) << 3);// row within n16 pair
    const int b_c = ((lane >> 3) & 1) << 3;         // 0 or 8 (k offset)

    const int bm = blockIdx.y, bn = blockIdx.x;
    const __nv_bfloat16* Ahi_b = Ahi + (long)bm * 128 * K;
    const __nv_bfloat16* Alo_b = Alo + (long)bm * 128 * K;
    const __nv_bfloat16* Bhi_b = Bhi + (long)bn * 256 * K;
    const __nv_bfloat16* Blo_b = Blo + (long)bn * 256 * K;

    auto sA = [&](int st, int p) -> __nv_bfloat16* {
        return smem + st * STAGE_E + p * AP_E;
    };
    auto sB = [&](int st, int p) -> __nv_bfloat16* {
        return smem + st * STAGE_E + 2 * AP_E + p * BP_E;
    };

    auto ld_tile = [&](int st, int kt) {
        long k0 = (long)kt * 32;
        #pragma unroll
        for (int i = 0; i < 2; i++) {
            int c = tid + i * 256;
            int row = c >> 2, ch = (c & 3) * 8;
            long go = (long)row * K + k0 + ch;
            int  so = row * KPAD + ch;
            cp16(sA(st,0) + so, Ahi_b + go);
            cp16(sA(st,1) + so, Alo_b + go);
        }
        #pragma unroll
        for (int i = 0; i < 4; i++) {
            int c = tid + i * 256;
            int row = c >> 2, ch = (c & 3) * 8;
            long go = (long)row * K + k0 + ch;
            int  so = row * KPAD + ch;
            cp16(sB(st,0) + so, Bhi_b + go);
            cp16(sB(st,1) + so, Blo_b + go);
        }
    };

    float acc[4][8][4];
    #pragma unroll
    for (int i = 0; i < 4; i++)
        #pragma unroll
        for (int j = 0; j < 8; j++)
            #pragma unroll
            for (int r = 0; r < 4; r++) acc[i][j][r] = 0.f;

    const int KT = K / 32;
    ld_tile(0, 0); CP_COMMIT();
    ld_tile(1, 1); CP_COMMIT();

    int st = 0;
    for (int kt = 0; kt < KT; kt++) {
        if (kt + 1 < KT) { CP_WAIT1(); } else { CP_WAIT0(); }
        __syncthreads();
        if (kt + 2 < KT) {
            int wst = st + 2; if (wst >= 3) wst -= 3;
            ld_tile(wst, kt + 2);
            CP_COMMIT();
        }

        const __nv_bfloat16* sAh = sA(st, 0);
        const __nv_bfloat16* sAl = sA(st, 1);
        const __nv_bfloat16* sBh = sB(st, 0);
        const __nv_bfloat16* sBl = sB(st, 1);

        #pragma unroll
        for (int ks = 0; ks < 2; ks++) {
            const int k16 = ks * 16;
            uint32_t ah[4][4], al[4][4], bh[8][2], bl[8][2];
            #pragma unroll
            for (int mt = 0; mt < 4; mt++) {
                int row = wm * 64 + mt * 16 + a_r;
                ldmx4(ah[mt], sAh + row * KPAD + k16 + a_c);
                ldmx4(al[mt], sAl + row * KPAD + k16 + a_c);
            }
            #pragma unroll
            for (int np = 0; np < 4; np++) {
                int row = wn * 64 + np * 16 + b_r;
                uint32_t r[4];
                ldmx4(r, sBh + row * KPAD + k16 + b_c);
                bh[2*np][0] = r[0]; bh[2*np][1] = r[1];
                bh[2*np+1][0] = r[2]; bh[2*np+1][1] = r[3];
                ldmx4(r, sBl + row * KPAD + k16 + b_c);
                bl[2*np][0] = r[0]; bl[2*np][1] = r[1];
                bl[2*np+1][0] = r[2]; bl[2*np+1][1] = r[3];
            }
            #pragma unroll
            for (int mt = 0; mt < 4; mt++)
                #pragma unroll
                for (int nt = 0; nt < 8; nt++) {
                    mma16816(acc[mt][nt], ah[mt], bh[nt]);
                    mma16816(acc[mt][nt], ah[mt], bl[nt]);
                    mma16816(acc[mt][nt], al[mt], bh[nt]);
                }
        }
        if (++st == 3) st = 0;
    }

    // epilogue
    const int lr4 = lane >> 2;
    const int lc2 = (lane & 3) * 2;
    #pragma unroll
    for (int mt = 0; mt < 4; mt++) {
        #pragma unroll
        for (int nt = 0; nt < 8; nt++) {
            int c = bn * 256 + wn * 64 + nt * 8 + lc2;
            #pragma unroll
            for (int half = 0; half < 2; half++) {
                int r = bm * 128 + wm * 64 + mt * 16 + lr4 + half * 8;
                float v0 = acc[mt][nt][half * 2 + 0];
                float v1 = acc[mt][nt][half * 2 + 1];
                long off = (long)r * N + c;
                if (EPI == 2) {
                    float2 bv = *(const float2*)(bias + c);
                    float2 rv = *(const float2*)(res + off);
                    *(float2*)(C + off) = make_float2(v0 + bv.x + rv.x,
                                                      v1 + bv.y + rv.y);
                } else if (EPI == 3) {
                    float2 bv = *(const float2*)(bias + c);
                    v0 = fmaxf(v0 + bv.x, 0.f);
                    v1 = fmaxf(v1 + bv.y, 0.f);
                    uint32_t lo;
                    uint32_t hi = pack2(v0, v1, lo);
                    *(uint32_t*)(Chi + off) = hi;
                    *(uint32_t*)(Clo + off) = lo;
                } else {  // EPI == 4
                    float scale = (c < Dq) ? ATT_SCALE : 1.f;
                    uint32_t lo;
                    uint32_t hi = pack2(v0 * scale, v1 * scale, lo);
                    *(uint32_t*)(Chi + off) = hi;
                    *(uint32_t*)(Clo + off) = lo;
                }
            }
        }
    }
}

// ---------------------------------------------------------------------------
// Tensor-core flash attention (bf16x3): ldmatrix fragments, hoisted Q frags,
// single barrier per KV tile.
// ---------------------------------------------------------------------------
#define FPAD 72
#define FLASH_SMEM ((2 * 128 * FPAD + 2 * 4 * 64 * FPAD) * 2)

__global__ void __launch_bounds__(256)
flash_tc(const __nv_bfloat16* __restrict__ qkvh,
         const __nv_bfloat16* __restrict__ qkvl,
         __nv_bfloat16* __restrict__ out_hi,
         __nv_bfloat16* __restrict__ out_lo)
{
    extern __shared__ __nv_bfloat16 sm[];
    __nv_bfloat16* QH = sm;
    __nv_bfloat16* QL = sm + 128 * FPAD;

    const int qi  = gridDim.x - 1 - blockIdx.x;
    const int bh  = blockIdx.y;
    const int b   = bh >> 4;
    const int h   = bh & 15;
    const int tid  = threadIdx.x;
    const int lane = tid & 31;
    const int warp = tid >> 5;
    const int g  = lane >> 2;
    const int t2 = (lane & 3) * 2;

    // ldmatrix per-lane offsets
    const int a_r = lane & 15;
    const int a_c = (lane >> 4) << 3;
    const int b_r = (lane & 7) + ((lane >> 4) << 3);
    const int b_c = ((lane >> 3) & 1) << 3;

    const long rb = (long)b * Tq;
    const __nv_bfloat16* qh = qkvh + (rb + qi * 128) * (3 * Dq) + h * HDq;
    const __nv_bfloat16* ql = qkvl + (rb + qi * 128) * (3 * Dq) + h * HDq;
    const __nv_bfloat16* kh = qkvh + rb * (3 * Dq) + Dq + h * HDq;
    const __nv_bfloat16* kl = qkvl + rb * (3 * Dq) + Dq + h * HDq;
    const __nv_bfloat16* vh = qkvh + rb * (3 * Dq) + 2 * Dq + h * HDq;
    const __nv_bfloat16* vl = qkvl + rb * (3 * Dq) + 2 * Dq + h * HDq;

    auto kvbase = [&](int st) -> __nv_bfloat16* {
        return sm + 2 * 128 * FPAD + st * (4 * 64 * FPAD);
    };
    auto ldkv = [&](int st, int jt) {
        __nv_bfloat16* KB = kvbase(st);
        #pragma unroll
        for (int i = 0; i < 2; i++) {
            int c = tid + i * 256;
            int row = c >> 3;
            int c8 = (c & 7) * 8;
            long go = (long)(jt * 64 + row) * (3 * Dq) + c8;
            int so = row * FPAD + c8;
            cp16(KB + so,                 kh + go);
            cp16(KB + 64 * FPAD + so,     kl + go);
            cp16(KB + 2 * 64 * FPAD + so, vh + go);
            cp16(KB + 3 * 64 * FPAD + so, vl + go);
        }
    };

    #pragma unroll
    for (int i = 0; i < 4; i++) {
        int c = tid + i * 256;
        int row = c >> 3;
        int c8 = (c & 7) * 8;
        cp16(QH + row * FPAD + c8, qh + (long)row * (3 * Dq) + c8);
        cp16(QL + row * FPAD + c8, ql + (long)row * (3 * Dq) + c8);
    }
    ldkv(0, 0);
    CP_COMMIT();

    float oacc[8][4];
    #pragma unroll
    for (int nt = 0; nt < 8; nt++)
        #pragma unroll
        for (int e = 0; e < 4; e++) oacc[nt][e] = 0.f;
    float m0 = -1e30f, m1 = -1e30f, l0 = 0.f, l1 = 0.f;

    uint32_t qfh[4][4], qfl[4][4];    // hoisted Q fragments (4 k-steps)

    const int qrow0 = qi * 128 + warp * 16 + g;
    const int jmax = 2 * qi + 1;

    for (int jt = 0; jt <= jmax; jt++) {
        CP_WAIT0();
        __syncthreads();
        if (jt < jmax) { ldkv((jt + 1) & 1, jt + 1); CP_COMMIT(); }

        if (jt == 0) {
            // Q fragments: load once, reuse for every KV tile
            #pragma unroll
            for (int kt = 0; kt < 4; kt++) {
                int row = warp * 16 + a_r;
                ldmx4(qfh[kt], QH + row * FPAD + kt * 16 + a_c);
                ldmx4(qfl[kt], QL + row * FPAD + kt * 16 + a_c);
            }
        }

        if (jt * 64 <= qi * 128 + warp * 16 + 15) {
            __nv_bfloat16* KB = kvbase(jt & 1);
            const __nv_bfloat16* KHs = KB;
            const __nv_bfloat16* KLs = KB + 64 * FPAD;
            const __nv_bfloat16* VHs = KB + 2 * 64 * FPAD;
            const __nv_bfloat16* VLs = KB + 3 * 64 * FPAD;

            float sacc[8][4];
            #pragma unroll
            for (int nt = 0; nt < 8; nt++)
                #pragma unroll
                for (int e = 0; e < 4; e++) sacc[nt][e] = 0.f;

            #pragma unroll
            for (int kt = 0; kt < 4; kt++) {
                uint32_t bh2[8][2], bl2[8][2];
                #pragma unroll
                for (int np = 0; np < 4; np++) {
                    int row = np * 16 + b_r;
                    uint32_t r[4];
                    ldmx4(r, KHs + row * FPAD + kt * 16 + b_c);
                    bh2[2*np][0] = r[0]; bh2[2*np][1] = r[1];
                    bh2[2*np+1][0] = r[2]; bh2[2*np+1][1] = r[3];
                    ldmx4(r, KLs + row * FPAD + kt * 16 + b_c);
                    bl2[2*np][0] = r[0]; bl2[2*np][1] = r[1];
                    bl2[2*np+1][0] = r[2]; bl2[2*np+1][1] = r[3];
                }
                #pragma unroll
                for (int nt = 0; nt < 8; nt++) {
                    mma16816(sacc[nt], qfh[kt], bh2[nt]);
                    mma16816(sacc[nt], qfh[kt], bl2[nt]);
                    mma16816(sacc[nt], qfl[kt], bh2[nt]);
                }
            }

            if (jt * 64 + 63 > qrow0) {
                #pragma unroll
                for (int nt = 0; nt < 8; nt++) {
                    int key0 = jt * 64 + nt * 8 + t2;
                    if (key0     > qrow0)     sacc[nt][0] = -1e30f;
                    if (key0 + 1 > qrow0)     sacc[nt][1] = -1e30f;
                    if (key0     > qrow0 + 8) sacc[nt][2] = -1e30f;
                    if (key0 + 1 > qrow0 + 8) sacc[nt][3] = -1e30f;
                }
            }

            float mx0 = -1e30f, mx1 = -1e30f;
            #pragma unroll
            for (int nt = 0; nt < 8; nt++) {
                mx0 = fmaxf(mx0, fmaxf(sacc[nt][0], sacc[nt][1]));
                mx1 = fmaxf(mx1, fmaxf(sacc[nt][2], sacc[nt][3]));
            }
            mx0 = fmaxf(mx0, __shfl_xor_sync(0xffffffffu, mx0, 1));
            mx0 = fmaxf(mx0, __shfl_xor_sync(0xffffffffu, mx0, 2));
            mx1 = fmaxf(mx1, __shfl_xor_sync(0xffffffffu, mx1, 1));
            mx1 = fmaxf(mx1, __shfl_xor_sync(0xffffffffu, mx1, 2));
            float mn0 = fmaxf(m0, mx0), mn1 = fmaxf(m1, mx1);
            float a0 = __expf(m0 - mn0), a1 = __expf(m1 - mn1);
            m0 = mn0; m1 = mn1;
            float rs0 = 0.f, rs1 = 0.f;
            #pragma unroll
            for (int nt = 0; nt < 8; nt++) {
                sacc[nt][0] = __expf(sacc[nt][0] - mn0); rs0 += sacc[nt][0];
                sacc[nt][1] = __expf(sacc[nt][1] - mn0); rs0 += sacc[nt][1];
                sacc[nt][2] = __expf(sacc[nt][2] - mn1); rs1 += sacc[nt][2];
                sacc[nt][3] = __expf(sacc[nt][3] - mn1); rs1 += sacc[nt][3];
            }
            rs0 += __shfl_xor_sync(0xffffffffu, rs0, 1);
            rs0 += __shfl_xor_sync(0xffffffffu, rs0, 2);
            rs1 += __shfl_xor_sync(0xffffffffu, rs1, 1);
            rs1 += __shfl_xor_sync(0xffffffffu, rs1, 2);
            l0 = l0 * a0 + rs0;
            l1 = l1 * a1 + rs1;
            #pragma unroll
            for (int nt = 0; nt < 8; nt++) {
                oacc[nt][0] *= a0; oacc[nt][1] *= a0;
                oacc[nt][2] *= a1; oacc[nt][3] *= a1;
            }

            #pragma unroll
            for (int j = 0; j < 4; j++) {
                uint32_t ph[4], pl4[4];
                ph[0] = pack2(sacc[2*j][0],   sacc[2*j][1],   pl4[0]);
                ph[1] = pack2(sacc[2*j][2],   sacc[2*j][3],   pl4[1]);
                ph[2] = pack2(sacc[2*j+1][0], sacc[2*j+1][1], pl4[2]);
                ph[3] = pack2(sacc[2*j+1][2], sacc[2*j+1][3], pl4[3]);
                #pragma unroll
                for (int nt = 0; nt < 8; nt++) {
                    uint32_t vhf[2], vlf[2];
                    ldmx2t(vhf[0], vhf[1], VHs + (j * 16 + (lane & 15)) * FPAD + nt * 8);
                    ldmx2t(vlf[0], vlf[1], VLs + (j * 16 + (lane & 15)) * FPAD + nt * 8);
                    mma16816(oacc[nt], ph, vhf);
                    mma16816(oacc[nt], ph, vlf);
                    mma16816(oacc[nt], pl4, vhf);
                }
            }
        }
    }

    float inv0 = 1.f / l0, inv1 = 1.f / l1;
    long row0 = (long)b * Tq + qi * 128 + warp * 16 + g;
    #pragma unroll
    for (int nt = 0; nt < 8; nt++) {
        int col = h * HDq + nt * 8 + t2;
        uint32_t lo;
        uint32_t hi = pack2(oacc[nt][0] * inv0, oacc[nt][1] * inv0, lo);
        *(uint32_t*)(out_hi + row0 * Dq + col) = hi;
        *(uint32_t*)(out_lo + row0 * Dq + col) = lo;
        hi = pack2(oacc[nt][2] * inv1, oacc[nt][3] * inv1, lo);
        *(uint32_t*)(out_hi + (row0 + 8) * Dq + col) = hi;
        *(uint32_t*)(out_lo + (row0 + 8) * Dq + col) = lo;
    }
}

// ---------------------------------------------------------------------------
// Launch
// ---------------------------------------------------------------------------
extern "C" void kernel_launch(void* const* d_in, const int* in_sizes, int n_in,
                              void* d_out, int out_size)
{
    const float* x   = (const float*)d_in[0];
    const float* Wq  = (const float*)d_in[1];
    const float* Wk  = (const float*)d_in[2];
    const float* Wv  = (const float*)d_in[3];
    const float* Wp  = (const float*)d_in[4];
    const float* bp  = (const float*)d_in[5];
    const float* W1  = (const float*)d_in[6];
    const float* b1  = (const float*)d_in[7];
    const float* W2  = (const float*)d_in[8];
    const float* b2  = (const float*)d_in[9];
    const float* g1  = (const float*)d_in[10];
    const float* be1 = (const float*)d_in[11];
    const float* g2  = (const float*)d_in[12];
    const float* be2 = (const float*)d_in[13];
    float* out = (float*)d_out;

    __nv_bfloat16 *p_h_hi, *p_h_lo, *p_wqkv_hi, *p_wqkv_lo, *p_wp_hi, *p_wp_lo;
    __nv_bfloat16 *p_w1_hi, *p_w1_lo, *p_w2_hi, *p_w2_lo;
    __nv_bfloat16 *p_attn_hi, *p_attn_lo, *p_ff_hi, *p_ff_lo, *p_qkvh, *p_qkvl;
    float *p_x1;
    cudaGetSymbolAddress((void**)&p_h_hi,    g_h_hi);
    cudaGetSymbolAddress((void**)&p_h_lo,    g_h_lo);
    cudaGetSymbolAddress((void**)&p_wqkv_hi, g_wqkv_hi);
    cudaGetSymbolAddress((void**)&p_wqkv_lo, g_wqkv_lo);
    cudaGetSymbolAddress((void**)&p_wp_hi,   g_wp_hi);
    cudaGetSymbolAddress((void**)&p_wp_lo,   g_wp_lo);
    cudaGetSymbolAddress((void**)&p_w1_hi,   g_w1_hi);
    cudaGetSymbolAddress((void**)&p_w1_lo,   g_w1_lo);
    cudaGetSymbolAddress((void**)&p_w2_hi,   g_w2_hi);
    cudaGetSymbolAddress((void**)&p_w2_lo,   g_w2_lo);
    cudaGetSymbolAddress((void**)&p_qkvh,    g_qkvh);
    cudaGetSymbolAddress((void**)&p_qkvl,    g_qkvl);
    cudaGetSymbolAddress((void**)&p_attn_hi, g_attn_hi);
    cudaGetSymbolAddress((void**)&p_attn_lo, g_attn_lo);
    cudaGetSymbolAddress((void**)&p_x1,      g_x1);
    cudaGetSymbolAddress((void**)&p_ff_hi,   g_ff_hi);
    cudaGetSymbolAddress((void**)&p_ff_lo,   g_ff_lo);

    cudaFuncSetAttribute(gemm_bf16x3<2>, cudaFuncAttributeMaxDynamicSharedMemorySize, GEMM_SMEM);
    cudaFuncSetAttribute(gemm_bf16x3<3>, cudaFuncAttributeMaxDynamicSharedMemorySize, GEMM_SMEM);
    cudaFuncSetAttribute(gemm_bf16x3<4>, cudaFuncAttributeMaxDynamicSharedMemorySize, GEMM_SMEM);
    cudaFuncSetAttribute(flash_tc,       cudaFuncAttributeMaxDynamicSharedMemorySize, FLASH_SMEM);

    // weight prep
    prep_wqkv_tiled<<<dim3(HDq / 32, Dq / 32, 48), dim3(32, 8)>>>(Wq, Wk, Wv, p_wqkv_hi, p_wqkv_lo);
    transpose_split_t<<<dim3(Dq / 32, Dq / 32),  dim3(32, 8)>>>(Wp, p_wp_hi, p_wp_lo, Dq, Dq);
    transpose_split_t<<<dim3(DFF / 32, Dq / 32), dim3(32, 8)>>>(W1, p_w1_hi, p_w1_lo, Dq, DFF);
    transpose_split_t<<<dim3(Dq / 32, DFF / 32), dim3(32, 8)>>>(W2, p_w2_hi, p_w2_lo, DFF, Dq);

    // LN1
    ln_split_kernel<<<Mq, 256>>>(x, g1, be1, p_h_hi, p_h_lo);
    // QKV projection -> split bf16, q prescaled
    gemm_bf16x3<4><<<dim3(3 * Dq / 256, Mq / 128), 256, GEMM_SMEM>>>(
        p_h_hi, p_h_lo, p_wqkv_hi, p_wqkv_lo, nullptr, nullptr,
        nullptr, p_qkvh, p_qkvl, 3 * Dq, Dq);
    // flash attention
    flash_tc<<<dim3(Tq / 128, Bq * Hq), 256, FLASH_SMEM>>>(
        p_qkvh, p_qkvl, p_attn_hi, p_attn_lo);
    // output projection + bias + residual(x)
    gemm_bf16x3<2><<<dim3(Dq / 256, Mq / 128), 256, GEMM_SMEM>>>(
        p_attn_hi, p_attn_lo, p_wp_hi, p_wp_lo, bp, x,
        p_x1, nullptr, nullptr, Dq, Dq);
    // LN2
    ln_split_kernel<<<Mq, 256>>>(p_x1, g2, be2, p_h_hi, p_h_lo);
    // FFN up + bias + relu
    gemm_bf16x3<3><<<dim3(DFF / 256, Mq / 128), 256, GEMM_SMEM>>>(
        p_h_hi, p_h_lo, p_w1_hi, p_w1_lo, b1, nullptr,
        nullptr, p_ff_hi, p_ff_lo, DFF, Dq);
    // FFN down + bias + residual(x1) -> d_out
    gemm_bf16x3<2><<<dim3(Dq / 256, Mq / 128), 256, GEMM_SMEM>>>(
        p_ff_hi, p_ff_lo, p_w2_hi, p_w2_lo, b2, p_x1,
        out, nullptr, nullptr, Dq, DFF);
}